// round 7
// baseline (speedup 1.0000x reference)
#include <cuda_runtime.h>
#include <cuda_bf16.h>
#include <cstdint>

// Problem constants
#define BATCH   4
#define SEQ     4096
#define DMODEL  1024
#define HEAD    64

// Scratch for projected q/k/v heads: [B, S, H] fp32 each (4 MB each)
__device__ float g_qh[BATCH * SEQ * HEAD];
__device__ float g_kh[BATCH * SEQ * HEAD];
__device__ float g_vh[BATCH * SEQ * HEAD];

// ---------------------------------------------------------------------------
// Kernel 1: fused projections  out[b,s,:] = x[b,s,:] @ W   (three in one grid.z)
// Block tile: 64 rows x 64 cols (full H), K chunks of 64. 256 threads, 4x4 micro.
// ---------------------------------------------------------------------------
__global__ __launch_bounds__(256) void proj_kernel(
    const float* __restrict__ q, const float* __restrict__ k, const float* __restrict__ v,
    const float* __restrict__ wq, const float* __restrict__ wk, const float* __restrict__ wv)
{
    __shared__ float a_s[64 * 68];   // x tile, padded rows (68 floats)
    __shared__ float w_s[64 * 64];   // w chunk [d][h]

    const int z = blockIdx.z;
    const float* x = (z == 0) ? q : (z == 1) ? k : v;
    const float* w = (z == 0) ? wq : (z == 1) ? wk : wv;
    float* out     = (z == 0) ? g_qh : (z == 1) ? g_kh : g_vh;

    const int row0 = blockIdx.x * 64;
    const int tid  = threadIdx.x;
    const int tx   = tid & 15;        // 16 col groups (4 cols each)
    const int ty   = tid >> 4;        // 16 row groups (4 rows each)

    float acc[4][4] = {};

    for (int k0 = 0; k0 < DMODEL; k0 += 64) {
        // load 64x64 x-tile and 64x64 w-chunk (float4, coalesced)
        #pragma unroll
        for (int r = 0; r < 4; r++) {
            int f  = tid + 256 * r;       // float4 index 0..1023
            int rr = f >> 4;
            int c4 = f & 15;
            float4 av = *(const float4*)&x[(size_t)(row0 + rr) * DMODEL + k0 + c4 * 4];
            *(float4*)&a_s[rr * 68 + c4 * 4] = av;
            float4 bv = *(const float4*)&w[(size_t)(k0 + rr) * HEAD + c4 * 4];
            *(float4*)&w_s[rr * 64 + c4 * 4] = bv;
        }
        __syncthreads();

        #pragma unroll
        for (int d4 = 0; d4 < 16; d4++) {
            float4 b0 = *(const float4*)&w_s[(d4 * 4 + 0) * 64 + tx * 4];
            float4 b1 = *(const float4*)&w_s[(d4 * 4 + 1) * 64 + tx * 4];
            float4 b2 = *(const float4*)&w_s[(d4 * 4 + 2) * 64 + tx * 4];
            float4 b3 = *(const float4*)&w_s[(d4 * 4 + 3) * 64 + tx * 4];
            #pragma unroll
            for (int i = 0; i < 4; i++) {
                float4 a = *(const float4*)&a_s[(ty * 4 + i) * 68 + d4 * 4];
                acc[i][0] += a.x * b0.x + a.y * b1.x + a.z * b2.x + a.w * b3.x;
                acc[i][1] += a.x * b0.y + a.y * b1.y + a.z * b2.y + a.w * b3.y;
                acc[i][2] += a.x * b0.z + a.y * b1.z + a.z * b2.z + a.w * b3.z;
                acc[i][3] += a.x * b0.w + a.y * b1.w + a.z * b2.w + a.w * b3.w;
            }
        }
        __syncthreads();
    }

    #pragma unroll
    for (int i = 0; i < 4; i++) {
        float4 o = make_float4(acc[i][0], acc[i][1], acc[i][2], acc[i][3]);
        *(float4*)&out[(size_t)(row0 + ty * 4 + i) * HEAD + tx * 4] = o;
    }
}

// ---------------------------------------------------------------------------
// Kernel 2: causal flash attention, fp32 SIMT.
// Per block: 64 query rows x full head. K tiles of 64, online softmax.
// 256 threads = 16x16; thread owns 4 rows x 4 cols of S, 4 rows x 4 h of O.
// ---------------------------------------------------------------------------
__global__ __launch_bounds__(256) void attn_kernel(float* __restrict__ out)
{
    extern __shared__ float sm[];
    float* q_s = sm;                 // 64*68
    float* k_s = sm + 64 * 68;
    float* v_s = sm + 2 * 64 * 68;
    float* p_s = sm + 3 * 64 * 68;

    const int b   = blockIdx.y;
    const int qt  = gridDim.x - 1 - blockIdx.x;   // heavy (diagonal-far) tiles first
    const int tid = threadIdx.x;
    const int tx  = tid & 15;
    const int ty  = tid >> 4;

    const float* qh = g_qh + (size_t)b * SEQ * HEAD;
    const float* kh = g_kh + (size_t)b * SEQ * HEAD;
    const float* vh = g_vh + (size_t)b * SEQ * HEAD;

    // load q tile once
    #pragma unroll
    for (int r = 0; r < 4; r++) {
        int f  = tid + 256 * r;
        int rr = f >> 4;
        int c4 = f & 15;
        *(float4*)&q_s[rr * 68 + c4 * 4] =
            *(const float4*)&qh[(size_t)(qt * 64 + rr) * HEAD + c4 * 4];
    }

    float o[4][4] = {};
    float m[4], l[4];
    #pragma unroll
    for (int i = 0; i < 4; i++) { m[i] = -1e30f; l[i] = 0.0f; }

    const float scale = 0.125f;   // 1/sqrt(64)

    for (int n0 = 0; n0 <= qt; n0++) {
        __syncthreads();   // previous-iter p_s/k_s/v_s consumers done (also covers q_s load)

        // load K and V tiles [64 x 64]
        #pragma unroll
        for (int r = 0; r < 4; r++) {
            int f  = tid + 256 * r;
            int rr = f >> 4;
            int c4 = f & 15;
            size_t g = (size_t)(n0 * 64 + rr) * HEAD + c4 * 4;
            *(float4*)&k_s[rr * 68 + c4 * 4] = *(const float4*)&kh[g];
            *(float4*)&v_s[rr * 68 + c4 * 4] = *(const float4*)&vh[g];
        }
        __syncthreads();

        // S = Q K^T
        float s[4][4] = {};
        #pragma unroll
        for (int d4 = 0; d4 < 16; d4++) {
            float4 qv[4], kv[4];
            #pragma unroll
            for (int i = 0; i < 4; i++)
                qv[i] = *(const float4*)&q_s[(ty * 4 + i) * 68 + d4 * 4];
            #pragma unroll
            for (int j = 0; j < 4; j++)
                kv[j] = *(const float4*)&k_s[(tx * 4 + j) * 68 + d4 * 4];
            #pragma unroll
            for (int i = 0; i < 4; i++)
                #pragma unroll
                for (int j = 0; j < 4; j++)
                    s[i][j] += qv[i].x * kv[j].x + qv[i].y * kv[j].y +
                               qv[i].z * kv[j].z + qv[i].w * kv[j].w;
        }

        const bool diag = (n0 == qt);
        #pragma unroll
        for (int i = 0; i < 4; i++)
            #pragma unroll
            for (int j = 0; j < 4; j++) {
                s[i][j] *= scale;
                if (diag && (tx * 4 + j) > (ty * 4 + i)) s[i][j] = -1e30f;
            }

        // online softmax per row (16 threads share a row: shuffle-reduce width 16)
        #pragma unroll
        for (int i = 0; i < 4; i++) {
            float mx = fmaxf(fmaxf(s[i][0], s[i][1]), fmaxf(s[i][2], s[i][3]));
            #pragma unroll
            for (int off = 8; off >= 1; off >>= 1)
                mx = fmaxf(mx, __shfl_xor_sync(0xffffffffu, mx, off));
            float mn   = fmaxf(m[i], mx);
            float corr = __expf(m[i] - mn);
            m[i] = mn;
            float rs = 0.0f;
            #pragma unroll
            for (int j = 0; j < 4; j++) {
                s[i][j] = __expf(s[i][j] - mn);
                rs += s[i][j];
            }
            #pragma unroll
            for (int off = 8; off >= 1; off >>= 1)
                rs += __shfl_xor_sync(0xffffffffu, rs, off);
            l[i] = l[i] * corr + rs;
            #pragma unroll
            for (int j = 0; j < 4; j++) o[i][j] *= corr;
            *(float4*)&p_s[(ty * 4 + i) * 68 + tx * 4] =
                make_float4(s[i][0], s[i][1], s[i][2], s[i][3]);
        }
        __syncthreads();

        // O += P V
        #pragma unroll
        for (int c4 = 0; c4 < 16; c4++) {
            float pr[4][4];
            #pragma unroll
            for (int i = 0; i < 4; i++) {
                float4 t = *(const float4*)&p_s[(ty * 4 + i) * 68 + c4 * 4];
                pr[i][0] = t.x; pr[i][1] = t.y; pr[i][2] = t.z; pr[i][3] = t.w;
            }
            #pragma unroll
            for (int cc = 0; cc < 4; cc++) {
                float4 vv = *(const float4*)&v_s[(c4 * 4 + cc) * 68 + tx * 4];
                #pragma unroll
                for (int i = 0; i < 4; i++) {
                    o[i][0] += pr[i][cc] * vv.x;
                    o[i][1] += pr[i][cc] * vv.y;
                    o[i][2] += pr[i][cc] * vv.z;
                    o[i][3] += pr[i][cc] * vv.w;
                }
            }
        }
    }

    // epilogue: normalize and store
    #pragma unroll
    for (int i = 0; i < 4; i++) {
        float inv = 1.0f / l[i];
        float4 r = make_float4(o[i][0] * inv, o[i][1] * inv, o[i][2] * inv, o[i][3] * inv);
        *(float4*)&out[((size_t)b * SEQ + qt * 64 + ty * 4 + i) * HEAD + tx * 4] = r;
    }
}

// ---------------------------------------------------------------------------
extern "C" void kernel_launch(void* const* d_in, const int* in_sizes, int n_in,
                              void* d_out, int out_size)
{
    const float* q  = (const float*)d_in[0];
    const float* k  = (const float*)d_in[1];
    const float* v  = (const float*)d_in[2];
    const float* wq = (const float*)d_in[3];
    const float* wk = (const float*)d_in[4];
    const float* wv = (const float*)d_in[5];
    float* out = (float*)d_out;

    const int ATTN_SMEM = 4 * 64 * 68 * sizeof(float);   // 69632 B
    cudaFuncSetAttribute(attn_kernel, cudaFuncAttributeMaxDynamicSharedMemorySize, ATTN_SMEM);

    // projections: grid.x = (B*S)/64 row tiles, grid.z selects q/k/v
    proj_kernel<<<dim3((BATCH * SEQ) / 64, 1, 3), 256>>>(q, k, v, wq, wk, wv);

    // attention: one block per 64 query rows per batch
    attn_kernel<<<dim3(SEQ / 64, BATCH), 256, ATTN_SMEM>>>(out);
}

// round 8
// speedup vs baseline: 1.4197x; 1.4197x over previous
#include <cuda_runtime.h>
#include <cuda_bf16.h>
#include <cstdint>

// Problem constants
#define BATCH   4
#define SEQ     4096
#define DMODEL  1024
#define HEAD    64
#define NTILES  64          // SEQ / 64 query tiles per batch
#define CHUNK   16          // KV tiles (of 64 keys) per split-KV chunk
#define MAXC    4           // max chunks per query tile = NTILES/CHUNK

// Scratch for projected q/k/v heads: [B, S, H] fp32 each (4 MB each)
__device__ float g_qh[BATCH * SEQ * HEAD];
__device__ float g_kh[BATCH * SEQ * HEAD];
__device__ float g_vh[BATCH * SEQ * HEAD];

// Split-KV partials: O unnormalized [b][qt][c][64][64], m/l [b][qt][c][64]
__device__ float g_po[(size_t)BATCH * NTILES * MAXC * 64 * 64];
__device__ float g_pm[BATCH * NTILES * MAXC * 64];
__device__ float g_pl[BATCH * NTILES * MAXC * 64];

// ---------------------------------------------------------------------------
// Kernel 1: fused projections  out[b,s,:] = x[b,s,:] @ W   (three in one grid.z)
// ---------------------------------------------------------------------------
__global__ __launch_bounds__(256) void proj_kernel(
    const float* __restrict__ q, const float* __restrict__ k, const float* __restrict__ v,
    const float* __restrict__ wq, const float* __restrict__ wk, const float* __restrict__ wv)
{
    __shared__ float a_s[64 * 68];   // x tile, padded rows (68 floats)
    __shared__ float w_s[64 * 64];   // w chunk [d][h]

    const int z = blockIdx.z;
    const float* x = (z == 0) ? q : (z == 1) ? k : v;
    const float* w = (z == 0) ? wq : (z == 1) ? wk : wv;
    float* out     = (z == 0) ? g_qh : (z == 1) ? g_kh : g_vh;

    const int row0 = blockIdx.x * 64;
    const int tid  = threadIdx.x;
    const int tx   = tid & 15;
    const int ty   = tid >> 4;

    float acc[4][4] = {};

    for (int k0 = 0; k0 < DMODEL; k0 += 64) {
        #pragma unroll
        for (int r = 0; r < 4; r++) {
            int f  = tid + 256 * r;
            int rr = f >> 4;
            int c4 = f & 15;
            float4 av = *(const float4*)&x[(size_t)(row0 + rr) * DMODEL + k0 + c4 * 4];
            *(float4*)&a_s[rr * 68 + c4 * 4] = av;
            float4 bv = *(const float4*)&w[(size_t)(k0 + rr) * HEAD + c4 * 4];
            *(float4*)&w_s[rr * 64 + c4 * 4] = bv;
        }
        __syncthreads();

        #pragma unroll
        for (int d4 = 0; d4 < 16; d4++) {
            float4 b0 = *(const float4*)&w_s[(d4 * 4 + 0) * 64 + tx * 4];
            float4 b1 = *(const float4*)&w_s[(d4 * 4 + 1) * 64 + tx * 4];
            float4 b2 = *(const float4*)&w_s[(d4 * 4 + 2) * 64 + tx * 4];
            float4 b3 = *(const float4*)&w_s[(d4 * 4 + 3) * 64 + tx * 4];
            #pragma unroll
            for (int i = 0; i < 4; i++) {
                float4 a = *(const float4*)&a_s[(ty * 4 + i) * 68 + d4 * 4];
                acc[i][0] += a.x * b0.x + a.y * b1.x + a.z * b2.x + a.w * b3.x;
                acc[i][1] += a.x * b0.y + a.y * b1.y + a.z * b2.y + a.w * b3.y;
                acc[i][2] += a.x * b0.z + a.y * b1.z + a.z * b2.z + a.w * b3.z;
                acc[i][3] += a.x * b0.w + a.y * b1.w + a.z * b2.w + a.w * b3.w;
            }
        }
        __syncthreads();
    }

    #pragma unroll
    for (int i = 0; i < 4; i++) {
        float4 o = make_float4(acc[i][0], acc[i][1], acc[i][2], acc[i][3]);
        *(float4*)&out[(size_t)(row0 + ty * 4 + i) * HEAD + tx * 4] = o;
    }
}

// ---------------------------------------------------------------------------
// Kernel 2: split-KV causal flash attention partials, fp32 SIMT.
// Per block: 64 query rows x one KV chunk (<=16 tiles of 64 keys).
// Writes unnormalized O + running (m, l) to global scratch.
// grid.x enumerates (qt, chunk) pairs: 64 + 48 + 32 + 16 = 160 per batch.
// ---------------------------------------------------------------------------
__global__ __launch_bounds__(256) void attn_partial_kernel()
{
    extern __shared__ float sm[];
    float* q_s = sm;                 // 64*68
    float* k_s = sm + 64 * 68;
    float* v_s = sm + 2 * 64 * 68;
    float* p_s = sm + 3 * 64 * 68;

    const int b  = blockIdx.y;
    const int bx = blockIdx.x;
    int qt, c;
    if      (bx <  64) { c = 0; qt = bx; }
    else if (bx < 112) { c = 1; qt = 16 + (bx - 64); }
    else if (bx < 144) { c = 2; qt = 32 + (bx - 112); }
    else               { c = 3; qt = 48 + (bx - 144); }

    const int n_begin = c * CHUNK;
    const int n_end   = (qt < n_begin + CHUNK - 1) ? qt : (n_begin + CHUNK - 1);

    const int tid = threadIdx.x;
    const int tx  = tid & 15;
    const int ty  = tid >> 4;

    const float* qh = g_qh + (size_t)b * SEQ * HEAD;
    const float* kh = g_kh + (size_t)b * SEQ * HEAD;
    const float* vh = g_vh + (size_t)b * SEQ * HEAD;

    // load q tile once
    #pragma unroll
    for (int r = 0; r < 4; r++) {
        int f  = tid + 256 * r;
        int rr = f >> 4;
        int c4 = f & 15;
        *(float4*)&q_s[rr * 68 + c4 * 4] =
            *(const float4*)&qh[(size_t)(qt * 64 + rr) * HEAD + c4 * 4];
    }

    float o[4][4] = {};
    float m[4], l[4];
    #pragma unroll
    for (int i = 0; i < 4; i++) { m[i] = -1e30f; l[i] = 0.0f; }

    const float scale = 0.125f;   // 1/sqrt(64)

    for (int n0 = n_begin; n0 <= n_end; n0++) {
        __syncthreads();   // previous-iter p_s/k_s/v_s consumers done (also covers q_s load)

        // load K and V tiles [64 x 64]
        #pragma unroll
        for (int r = 0; r < 4; r++) {
            int f  = tid + 256 * r;
            int rr = f >> 4;
            int c4 = f & 15;
            size_t g = (size_t)(n0 * 64 + rr) * HEAD + c4 * 4;
            *(float4*)&k_s[rr * 68 + c4 * 4] = *(const float4*)&kh[g];
            *(float4*)&v_s[rr * 68 + c4 * 4] = *(const float4*)&vh[g];
        }
        __syncthreads();

        // S = Q K^T
        float s[4][4] = {};
        #pragma unroll
        for (int d4 = 0; d4 < 16; d4++) {
            float4 qv[4], kv[4];
            #pragma unroll
            for (int i = 0; i < 4; i++)
                qv[i] = *(const float4*)&q_s[(ty * 4 + i) * 68 + d4 * 4];
            #pragma unroll
            for (int j = 0; j < 4; j++)
                kv[j] = *(const float4*)&k_s[(tx * 4 + j) * 68 + d4 * 4];
            #pragma unroll
            for (int i = 0; i < 4; i++)
                #pragma unroll
                for (int j = 0; j < 4; j++)
                    s[i][j] += qv[i].x * kv[j].x + qv[i].y * kv[j].y +
                               qv[i].z * kv[j].z + qv[i].w * kv[j].w;
        }

        const bool diag = (n0 == qt);
        #pragma unroll
        for (int i = 0; i < 4; i++)
            #pragma unroll
            for (int j = 0; j < 4; j++) {
                s[i][j] *= scale;
                if (diag && (tx * 4 + j) > (ty * 4 + i)) s[i][j] = -1e30f;
            }

        // online softmax per row (16 threads share a row: shuffle-reduce width 16)
        #pragma unroll
        for (int i = 0; i < 4; i++) {
            float mx = fmaxf(fmaxf(s[i][0], s[i][1]), fmaxf(s[i][2], s[i][3]));
            #pragma unroll
            for (int off = 8; off >= 1; off >>= 1)
                mx = fmaxf(mx, __shfl_xor_sync(0xffffffffu, mx, off));
            float mn   = fmaxf(m[i], mx);
            float corr = __expf(m[i] - mn);
            m[i] = mn;
            float rs = 0.0f;
            #pragma unroll
            for (int j = 0; j < 4; j++) {
                s[i][j] = __expf(s[i][j] - mn);
                rs += s[i][j];
            }
            #pragma unroll
            for (int off = 8; off >= 1; off >>= 1)
                rs += __shfl_xor_sync(0xffffffffu, rs, off);
            l[i] = l[i] * corr + rs;
            #pragma unroll
            for (int j = 0; j < 4; j++) o[i][j] *= corr;
            *(float4*)&p_s[(ty * 4 + i) * 68 + tx * 4] =
                make_float4(s[i][0], s[i][1], s[i][2], s[i][3]);
        }
        __syncthreads();

        // O += P V
        #pragma unroll
        for (int c4 = 0; c4 < 16; c4++) {
            float pr[4][4];
            #pragma unroll
            for (int i = 0; i < 4; i++) {
                float4 t = *(const float4*)&p_s[(ty * 4 + i) * 68 + c4 * 4];
                pr[i][0] = t.x; pr[i][1] = t.y; pr[i][2] = t.z; pr[i][3] = t.w;
            }
            #pragma unroll
            for (int cc = 0; cc < 4; cc++) {
                float4 vv = *(const float4*)&v_s[(c4 * 4 + cc) * 68 + tx * 4];
                #pragma unroll
                for (int i = 0; i < 4; i++) {
                    o[i][0] += pr[i][cc] * vv.x;
                    o[i][1] += pr[i][cc] * vv.y;
                    o[i][2] += pr[i][cc] * vv.z;
                    o[i][3] += pr[i][cc] * vv.w;
                }
            }
        }
    }

    // epilogue: write unnormalized partial O and (m, l)
    const size_t slot = ((size_t)b * NTILES + qt) * MAXC + c;
    float* po = g_po + slot * (64 * 64);
    #pragma unroll
    for (int i = 0; i < 4; i++) {
        *(float4*)&po[(ty * 4 + i) * 64 + tx * 4] =
            make_float4(o[i][0], o[i][1], o[i][2], o[i][3]);
    }
    if (tx == 0) {
        #pragma unroll
        for (int i = 0; i < 4; i++) {
            g_pm[slot * 64 + ty * 4 + i] = m[i];
            g_pl[slot * 64 + ty * 4 + i] = l[i];
        }
    }
}

// ---------------------------------------------------------------------------
// Kernel 3: merge split-KV partials. One block per (qt, b).
// out[r][h] = sum_c e^{m_c - M} O_c[r][h] / (sum_c e^{m_c - M} l_c)
// ---------------------------------------------------------------------------
__global__ __launch_bounds__(256) void attn_merge_kernel(float* __restrict__ out)
{
    const int b  = blockIdx.y;
    const int qt = blockIdx.x;
    const int nc = qt / CHUNK + 1;

    const int tid = threadIdx.x;
    const int tx  = tid & 15;
    const int ty  = tid >> 4;

    const size_t slot0 = ((size_t)b * NTILES + qt) * MAXC;

    #pragma unroll
    for (int i = 0; i < 4; i++) {
        const int r = ty * 4 + i;
        float M = -1e30f;
        for (int c = 0; c < nc; c++)
            M = fmaxf(M, g_pm[(slot0 + c) * 64 + r]);
        float L = 0.0f;
        float w[MAXC];
        for (int c = 0; c < nc; c++) {
            w[c] = __expf(g_pm[(slot0 + c) * 64 + r] - M);
            L += w[c] * g_pl[(slot0 + c) * 64 + r];
        }
        float4 acc = make_float4(0.f, 0.f, 0.f, 0.f);
        for (int c = 0; c < nc; c++) {
            const float4 t = *(const float4*)&g_po[(slot0 + c) * (64 * 64) + r * 64 + tx * 4];
            acc.x += w[c] * t.x; acc.y += w[c] * t.y;
            acc.z += w[c] * t.z; acc.w += w[c] * t.w;
        }
        const float inv = 1.0f / L;
        acc.x *= inv; acc.y *= inv; acc.z *= inv; acc.w *= inv;
        *(float4*)&out[((size_t)b * SEQ + qt * 64 + r) * HEAD + tx * 4] = acc;
    }
}

// ---------------------------------------------------------------------------
extern "C" void kernel_launch(void* const* d_in, const int* in_sizes, int n_in,
                              void* d_out, int out_size)
{
    const float* q  = (const float*)d_in[0];
    const float* k  = (const float*)d_in[1];
    const float* v  = (const float*)d_in[2];
    const float* wq = (const float*)d_in[3];
    const float* wk = (const float*)d_in[4];
    const float* wv = (const float*)d_in[5];
    float* out = (float*)d_out;

    const int ATTN_SMEM = 4 * 64 * 68 * sizeof(float);   // 69632 B
    cudaFuncSetAttribute(attn_partial_kernel, cudaFuncAttributeMaxDynamicSharedMemorySize, ATTN_SMEM);

    // projections: grid.x = (B*S)/64 row tiles, grid.z selects q/k/v
    proj_kernel<<<dim3((BATCH * SEQ) / 64, 1, 3), 256>>>(q, k, v, wq, wk, wv);

    // split-KV partials: 160 (qt,chunk) pairs per batch
    attn_partial_kernel<<<dim3(160, BATCH), 256, ATTN_SMEM>>>();

    // merge: one block per query tile per batch
    attn_merge_kernel<<<dim3(NTILES, BATCH), 256>>>(out);
}

// round 12
// speedup vs baseline: 1.5432x; 1.0869x over previous
#include <cuda_runtime.h>
#include <cuda_bf16.h>
#include <cstdint>

// Problem constants
#define BATCH   4
#define SEQ     4096
#define DMODEL  1024
#define HEAD    64
#define NTILES  64          // SEQ / 64 query tiles per batch
#define CHUNK   16          // KV tiles (of 64 keys) per split-KV chunk
#define MAXC    4           // max chunks per query tile = NTILES/CHUNK

// Scratch for projected q/k/v heads: [B, S, H] fp32 each (4 MB each)
__device__ float g_qh[BATCH * SEQ * HEAD];
__device__ float g_kh[BATCH * SEQ * HEAD];
__device__ float g_vh[BATCH * SEQ * HEAD];

// Split-KV partials: O unnormalized [b][qt][c][64][64], m/l [b][qt][c][64]
__device__ float g_po[(size_t)BATCH * NTILES * MAXC * 64 * 64];
__device__ float g_pm[BATCH * NTILES * MAXC * 64];
__device__ float g_pl[BATCH * NTILES * MAXC * 64];

// ---------------------------------------------------------------------------
// mma.sync m16n8k16 bf16 -> f32 (baseline PTX, works on plain sm_103 target)
// ---------------------------------------------------------------------------
__device__ __forceinline__ void mma16816(float* c, const uint32_t* a, const uint32_t* b) {
    asm volatile(
        "mma.sync.aligned.m16n8k16.row.col.f32.bf16.bf16.f32 "
        "{%0,%1,%2,%3}, {%4,%5,%6,%7}, {%8,%9}, {%0,%1,%2,%3};"
        : "+f"(c[0]), "+f"(c[1]), "+f"(c[2]), "+f"(c[3])
        : "r"(a[0]), "r"(a[1]), "r"(a[2]), "r"(a[3]), "r"(b[0]), "r"(b[1]));
}

__device__ __forceinline__ uint32_t pack_bf16x2_hi(float a, float b) {
    __nv_bfloat162 h = __floats2bfloat162_rn(a, b);
    return *(uint32_t*)&h;
}

// ===========================================================================
// Kernel 1: mma.sync bf16-split projections. D[128,64] = X[128,1024] @ W[1024,64]
// 256 threads = 8 warps; warp w owns rows [16w,16w+16) x all 64 cols.
// K chunks of 64, staged in smem as bf16 hi/lo; W staged transposed [n][k].
// 3 pairings per product: hi*hi + hi*lo + lo*hi  (fp32-class accuracy).
// ===========================================================================
// smem (dynamic, 55296 B):
//   A_hi [128][72] bf16 @ 0       (18432 B)
//   A_lo [128][72] bf16 @ 18432
//   B_hi [64][72]  bf16 @ 36864   (9216 B)   Bt[n][k]
//   B_lo [64][72]  bf16 @ 46080
#define PROJ_SMEM 55296

__global__ __launch_bounds__(256) void proj_mma_kernel(
    const float* __restrict__ q, const float* __restrict__ k, const float* __restrict__ v,
    const float* __restrict__ wq, const float* __restrict__ wk, const float* __restrict__ wv)
{
    extern __shared__ char smem[];
    __nv_bfloat16* Ah = (__nv_bfloat16*)(smem);
    __nv_bfloat16* Al = (__nv_bfloat16*)(smem + 18432);
    __nv_bfloat16* Bh = (__nv_bfloat16*)(smem + 36864);
    __nv_bfloat16* Bl = (__nv_bfloat16*)(smem + 46080);

    const int z = blockIdx.z;
    const float* x = (z == 0) ? q : (z == 1) ? k : v;
    const float* w = (z == 0) ? wq : (z == 1) ? wk : wv;
    float* out     = (z == 0) ? g_qh : (z == 1) ? g_kh : g_vh;

    const int row0 = blockIdx.x * 128;
    const int tid  = threadIdx.x;
    const int warp = tid >> 5;
    const int lane = tid & 31;
    const int g    = lane >> 2;     // 0..7  (fragment row group / B n index)
    const int qd   = lane & 3;      // 0..3  (fragment k pair index)

    float acc[8][4];
    #pragma unroll
    for (int nt = 0; nt < 8; nt++)
        #pragma unroll
        for (int i = 0; i < 4; i++) acc[nt][i] = 0.0f;

    for (int c = 0; c < 16; c++) {
        const int k0 = c * 64;
        __syncthreads();   // previous chunk's mma reads done

        // ---- stage A: 128x64 fp32 -> bf16 hi/lo, rows padded to 72 bf16 ----
        #pragma unroll
        for (int it = 0; it < 8; it++) {
            int f  = tid + 256 * it;       // float4 index: 128 rows x 16
            int rr = f >> 4;
            int c4 = f & 15;
            float4 v0 = *(const float4*)&x[(size_t)(row0 + rr) * DMODEL + k0 + c4 * 4];
            uint32_t h0 = pack_bf16x2_hi(v0.x, v0.y);
            uint32_t h1 = pack_bf16x2_hi(v0.z, v0.w);
            __nv_bfloat162 hh0 = *(__nv_bfloat162*)&h0;
            __nv_bfloat162 hh1 = *(__nv_bfloat162*)&h1;
            uint32_t l0 = pack_bf16x2_hi(v0.x - __bfloat162float(hh0.x),
                                         v0.y - __bfloat162float(hh0.y));
            uint32_t l1 = pack_bf16x2_hi(v0.z - __bfloat162float(hh1.x),
                                         v0.w - __bfloat162float(hh1.y));
            *(uint2*)&Ah[rr * 72 + c4 * 4] = make_uint2(h0, h1);
            *(uint2*)&Al[rr * 72 + c4 * 4] = make_uint2(l0, l1);
        }

        // ---- stage B transposed: Bt[n][d] = w[k0+d][n], hi/lo ----
        #pragma unroll
        for (int it = 0; it < 4; it++) {
            int idx = tid + 256 * it;      // float4 index: 64 d-rows x 16
            int d   = idx >> 4;
            int n4  = idx & 15;
            float4 v0 = *(const float4*)&w[(size_t)(k0 + d) * HEAD + n4 * 4];
            float vals[4] = {v0.x, v0.y, v0.z, v0.w};
            #pragma unroll
            for (int j = 0; j < 4; j++) {
                __nv_bfloat16 h = __float2bfloat16(vals[j]);
                __nv_bfloat16 l = __float2bfloat16(vals[j] - __bfloat162float(h));
                Bh[(n4 * 4 + j) * 72 + d] = h;
                Bl[(n4 * 4 + j) * 72 + d] = l;
            }
        }
        __syncthreads();

        // ---- MMA: 4 k-steps x 8 n-tiles x 3 pairings ----
        const int ar0 = (warp * 16 + g) * 72;
        const int ar1 = (warp * 16 + g + 8) * 72;
        #pragma unroll
        for (int ks = 0; ks < 4; ks++) {
            const int kb = ks * 16 + qd * 2;
            uint32_t ah[4], al[4];
            ah[0] = *(uint32_t*)&Ah[ar0 + kb];
            ah[1] = *(uint32_t*)&Ah[ar1 + kb];
            ah[2] = *(uint32_t*)&Ah[ar0 + kb + 8];
            ah[3] = *(uint32_t*)&Ah[ar1 + kb + 8];
            al[0] = *(uint32_t*)&Al[ar0 + kb];
            al[1] = *(uint32_t*)&Al[ar1 + kb];
            al[2] = *(uint32_t*)&Al[ar0 + kb + 8];
            al[3] = *(uint32_t*)&Al[ar1 + kb + 8];
            #pragma unroll
            for (int nt = 0; nt < 8; nt++) {
                const int br = (nt * 8 + g) * 72;
                uint32_t bh[2], bl[2];
                bh[0] = *(uint32_t*)&Bh[br + kb];
                bh[1] = *(uint32_t*)&Bh[br + kb + 8];
                bl[0] = *(uint32_t*)&Bl[br + kb];
                bl[1] = *(uint32_t*)&Bl[br + kb + 8];
                mma16816(acc[nt], ah, bh);
                mma16816(acc[nt], ah, bl);
                mma16816(acc[nt], al, bh);
            }
        }
    }

    // ---- epilogue: fragment -> gmem (float2 stores) ----
    const int r0 = row0 + warp * 16 + g;
    #pragma unroll
    for (int nt = 0; nt < 8; nt++) {
        const int col = nt * 8 + qd * 2;
        *(float2*)&out[(size_t)r0 * HEAD + col]       = make_float2(acc[nt][0], acc[nt][1]);
        *(float2*)&out[(size_t)(r0 + 8) * HEAD + col] = make_float2(acc[nt][2], acc[nt][3]);
    }
}

// ---------------------------------------------------------------------------
// Kernel 2: split-KV causal flash attention partials, fp32 SIMT. (unchanged, R8)
// ---------------------------------------------------------------------------
__global__ __launch_bounds__(256) void attn_partial_kernel()
{
    extern __shared__ float sm[];
    float* q_s = sm;                 // 64*68
    float* k_s = sm + 64 * 68;
    float* v_s = sm + 2 * 64 * 68;
    float* p_s = sm + 3 * 64 * 68;

    const int b  = blockIdx.y;
    const int bx = blockIdx.x;
    int qt, c;
    if      (bx <  64) { c = 0; qt = bx; }
    else if (bx < 112) { c = 1; qt = 16 + (bx - 64); }
    else if (bx < 144) { c = 2; qt = 32 + (bx - 112); }
    else               { c = 3; qt = 48 + (bx - 144); }

    const int n_begin = c * CHUNK;
    const int n_end   = (qt < n_begin + CHUNK - 1) ? qt : (n_begin + CHUNK - 1);

    const int tid = threadIdx.x;
    const int tx  = tid & 15;
    const int ty  = tid >> 4;

    const float* qh = g_qh + (size_t)b * SEQ * HEAD;
    const float* kh = g_kh + (size_t)b * SEQ * HEAD;
    const float* vh = g_vh + (size_t)b * SEQ * HEAD;

    #pragma unroll
    for (int r = 0; r < 4; r++) {
        int f  = tid + 256 * r;
        int rr = f >> 4;
        int c4 = f & 15;
        *(float4*)&q_s[rr * 68 + c4 * 4] =
            *(const float4*)&qh[(size_t)(qt * 64 + rr) * HEAD + c4 * 4];
    }

    float o[4][4] = {};
    float m[4], l[4];
    #pragma unroll
    for (int i = 0; i < 4; i++) { m[i] = -1e30f; l[i] = 0.0f; }

    const float scale = 0.125f;   // 1/sqrt(64)

    for (int n0 = n_begin; n0 <= n_end; n0++) {
        __syncthreads();

        #pragma unroll
        for (int r = 0; r < 4; r++) {
            int f  = tid + 256 * r;
            int rr = f >> 4;
            int c4 = f & 15;
            size_t g = (size_t)(n0 * 64 + rr) * HEAD + c4 * 4;
            *(float4*)&k_s[rr * 68 + c4 * 4] = *(const float4*)&kh[g];
            *(float4*)&v_s[rr * 68 + c4 * 4] = *(const float4*)&vh[g];
        }
        __syncthreads();

        float s[4][4] = {};
        #pragma unroll
        for (int d4 = 0; d4 < 16; d4++) {
            float4 qv[4], kv[4];
            #pragma unroll
            for (int i = 0; i < 4; i++)
                qv[i] = *(const float4*)&q_s[(ty * 4 + i) * 68 + d4 * 4];
            #pragma unroll
            for (int j = 0; j < 4; j++)
                kv[j] = *(const float4*)&k_s[(tx * 4 + j) * 68 + d4 * 4];
            #pragma unroll
            for (int i = 0; i < 4; i++)
                #pragma unroll
                for (int j = 0; j < 4; j++)
                    s[i][j] += qv[i].x * kv[j].x + qv[i].y * kv[j].y +
                               qv[i].z * kv[j].z + qv[i].w * kv[j].w;
        }

        const bool diag = (n0 == qt);
        #pragma unroll
        for (int i = 0; i < 4; i++)
            #pragma unroll
            for (int j = 0; j < 4; j++) {
                s[i][j] *= scale;
                if (diag && (tx * 4 + j) > (ty * 4 + i)) s[i][j] = -1e30f;
            }

        #pragma unroll
        for (int i = 0; i < 4; i++) {
            float mx = fmaxf(fmaxf(s[i][0], s[i][1]), fmaxf(s[i][2], s[i][3]));
            #pragma unroll
            for (int off = 8; off >= 1; off >>= 1)
                mx = fmaxf(mx, __shfl_xor_sync(0xffffffffu, mx, off));
            float mn   = fmaxf(m[i], mx);
            float corr = __expf(m[i] - mn);
            m[i] = mn;
            float rs = 0.0f;
            #pragma unroll
            for (int j = 0; j < 4; j++) {
                s[i][j] = __expf(s[i][j] - mn);
                rs += s[i][j];
            }
            #pragma unroll
            for (int off = 8; off >= 1; off >>= 1)
                rs += __shfl_xor_sync(0xffffffffu, rs, off);
            l[i] = l[i] * corr + rs;
            #pragma unroll
            for (int j = 0; j < 4; j++) o[i][j] *= corr;
            *(float4*)&p_s[(ty * 4 + i) * 68 + tx * 4] =
                make_float4(s[i][0], s[i][1], s[i][2], s[i][3]);
        }
        __syncthreads();

        #pragma unroll
        for (int c4 = 0; c4 < 16; c4++) {
            float pr[4][4];
            #pragma unroll
            for (int i = 0; i < 4; i++) {
                float4 t = *(const float4*)&p_s[(ty * 4 + i) * 68 + c4 * 4];
                pr[i][0] = t.x; pr[i][1] = t.y; pr[i][2] = t.z; pr[i][3] = t.w;
            }
            #pragma unroll
            for (int cc = 0; cc < 4; cc++) {
                float4 vv = *(const float4*)&v_s[(c4 * 4 + cc) * 68 + tx * 4];
                #pragma unroll
                for (int i = 0; i < 4; i++) {
                    o[i][0] += pr[i][cc] * vv.x;
                    o[i][1] += pr[i][cc] * vv.y;
                    o[i][2] += pr[i][cc] * vv.z;
                    o[i][3] += pr[i][cc] * vv.w;
                }
            }
        }
    }

    const size_t slot = ((size_t)b * NTILES + qt) * MAXC + c;
    float* po = g_po + slot * (64 * 64);
    #pragma unroll
    for (int i = 0; i < 4; i++) {
        *(float4*)&po[(ty * 4 + i) * 64 + tx * 4] =
            make_float4(o[i][0], o[i][1], o[i][2], o[i][3]);
    }
    if (tx == 0) {
        #pragma unroll
        for (int i = 0; i < 4; i++) {
            g_pm[slot * 64 + ty * 4 + i] = m[i];
            g_pl[slot * 64 + ty * 4 + i] = l[i];
        }
    }
}

// ---------------------------------------------------------------------------
// Kernel 3: merge split-KV partials. (unchanged, R8)
// ---------------------------------------------------------------------------
__global__ __launch_bounds__(256) void attn_merge_kernel(float* __restrict__ out)
{
    const int b  = blockIdx.y;
    const int qt = blockIdx.x;
    const int nc = qt / CHUNK + 1;

    const int tid = threadIdx.x;
    const int tx  = tid & 15;
    const int ty  = tid >> 4;

    const size_t slot0 = ((size_t)b * NTILES + qt) * MAXC;

    #pragma unroll
    for (int i = 0; i < 4; i++) {
        const int r = ty * 4 + i;
        float M = -1e30f;
        for (int c = 0; c < nc; c++)
            M = fmaxf(M, g_pm[(slot0 + c) * 64 + r]);
        float L = 0.0f;
        float w[MAXC];
        for (int c = 0; c < nc; c++) {
            w[c] = __expf(g_pm[(slot0 + c) * 64 + r] - M);
            L += w[c] * g_pl[(slot0 + c) * 64 + r];
        }
        float4 acc = make_float4(0.f, 0.f, 0.f, 0.f);
        for (int c = 0; c < nc; c++) {
            const float4 t = *(const float4*)&g_po[(slot0 + c) * (64 * 64) + r * 64 + tx * 4];
            acc.x += w[c] * t.x; acc.y += w[c] * t.y;
            acc.z += w[c] * t.z; acc.w += w[c] * t.w;
        }
        const float inv = 1.0f / L;
        acc.x *= inv; acc.y *= inv; acc.z *= inv; acc.w *= inv;
        *(float4*)&out[((size_t)b * SEQ + qt * 64 + r) * HEAD + tx * 4] = acc;
    }
}

// ---------------------------------------------------------------------------
extern "C" void kernel_launch(void* const* d_in, const int* in_sizes, int n_in,
                              void* d_out, int out_size)
{
    const float* q  = (const float*)d_in[0];
    const float* k  = (const float*)d_in[1];
    const float* v  = (const float*)d_in[2];
    const float* wq = (const float*)d_in[3];
    const float* wk = (const float*)d_in[4];
    const float* wv = (const float*)d_in[5];
    float* out = (float*)d_out;

    const int ATTN_SMEM = 4 * 64 * 68 * sizeof(float);   // 69632 B
    cudaFuncSetAttribute(attn_partial_kernel, cudaFuncAttributeMaxDynamicSharedMemorySize, ATTN_SMEM);
    cudaFuncSetAttribute(proj_mma_kernel, cudaFuncAttributeMaxDynamicSharedMemorySize, PROJ_SMEM);

    // mma.sync projections: 128-row tiles, grid.z selects q/k/v
    proj_mma_kernel<<<dim3((BATCH * SEQ) / 128, 1, 3), 256, PROJ_SMEM>>>(q, k, v, wq, wk, wv);

    // split-KV partials: 160 (qt,chunk) pairs per batch
    attn_partial_kernel<<<dim3(160, BATCH), 256, ATTN_SMEM>>>();

    // merge: one block per query tile per batch
    attn_merge_kernel<<<dim3(NTILES, BATCH), 256>>>(out);
}

// round 13
// speedup vs baseline: 3.3824x; 2.1918x over previous
#include <cuda_runtime.h>
#include <cuda_bf16.h>
#include <cstdint>

// Problem constants
#define BATCH   4
#define SEQ     4096
#define DMODEL  1024
#define HEAD    64
#define QT2     32          // SEQ / 128 query tiles per batch (mma attention)
#define NTILES  64
#define MAXC    4

// Scratch for projected q/k/v heads: [B, S, H] fp32 each (4 MB each)
__device__ float g_qh[BATCH * SEQ * HEAD];
__device__ float g_kh[BATCH * SEQ * HEAD];
__device__ float g_vh[BATCH * SEQ * HEAD];

// Split-KV partials (reinterpreted for 128-row tiles):
// O unnormalized [b][t][c][128][64], m/l [b][t][c][128]  (same total sizes)
__device__ float g_po[(size_t)BATCH * NTILES * MAXC * 64 * 64];
__device__ float g_pm[BATCH * NTILES * MAXC * 64];
__device__ float g_pl[BATCH * NTILES * MAXC * 64];

// ---------------------------------------------------------------------------
// mma.sync m16n8k16 bf16 -> f32 (baseline PTX, works on plain sm_103 target)
// ---------------------------------------------------------------------------
__device__ __forceinline__ void mma16816(float* c, const uint32_t* a, const uint32_t* b) {
    asm volatile(
        "mma.sync.aligned.m16n8k16.row.col.f32.bf16.bf16.f32 "
        "{%0,%1,%2,%3}, {%4,%5,%6,%7}, {%8,%9}, {%0,%1,%2,%3};"
        : "+f"(c[0]), "+f"(c[1]), "+f"(c[2]), "+f"(c[3])
        : "r"(a[0]), "r"(a[1]), "r"(a[2]), "r"(a[3]), "r"(b[0]), "r"(b[1]));
}

__device__ __forceinline__ uint32_t pack_bf16x2_hi(float a, float b) {
    __nv_bfloat162 h = __floats2bfloat162_rn(a, b);
    return *(uint32_t*)&h;
}

// ===========================================================================
// Kernel 1: mma.sync bf16-split projections. D[128,64] = X[128,1024] @ W[1024,64]
// (unchanged from R12 — passing at 143us)
// ===========================================================================
#define PROJ_SMEM 55296

__global__ __launch_bounds__(256) void proj_mma_kernel(
    const float* __restrict__ q, const float* __restrict__ k, const float* __restrict__ v,
    const float* __restrict__ wq, const float* __restrict__ wk, const float* __restrict__ wv)
{
    extern __shared__ char smem[];
    __nv_bfloat16* Ah = (__nv_bfloat16*)(smem);
    __nv_bfloat16* Al = (__nv_bfloat16*)(smem + 18432);
    __nv_bfloat16* Bh = (__nv_bfloat16*)(smem + 36864);
    __nv_bfloat16* Bl = (__nv_bfloat16*)(smem + 46080);

    const int z = blockIdx.z;
    const float* x = (z == 0) ? q : (z == 1) ? k : v;
    const float* w = (z == 0) ? wq : (z == 1) ? wk : wv;
    float* out     = (z == 0) ? g_qh : (z == 1) ? g_kh : g_vh;

    const int row0 = blockIdx.x * 128;
    const int tid  = threadIdx.x;
    const int warp = tid >> 5;
    const int lane = tid & 31;
    const int g    = lane >> 2;
    const int qd   = lane & 3;

    float acc[8][4];
    #pragma unroll
    for (int nt = 0; nt < 8; nt++)
        #pragma unroll
        for (int i = 0; i < 4; i++) acc[nt][i] = 0.0f;

    for (int c = 0; c < 16; c++) {
        const int k0 = c * 64;
        __syncthreads();

        #pragma unroll
        for (int it = 0; it < 8; it++) {
            int f  = tid + 256 * it;
            int rr = f >> 4;
            int c4 = f & 15;
            float4 v0 = *(const float4*)&x[(size_t)(row0 + rr) * DMODEL + k0 + c4 * 4];
            uint32_t h0 = pack_bf16x2_hi(v0.x, v0.y);
            uint32_t h1 = pack_bf16x2_hi(v0.z, v0.w);
            __nv_bfloat162 hh0 = *(__nv_bfloat162*)&h0;
            __nv_bfloat162 hh1 = *(__nv_bfloat162*)&h1;
            uint32_t l0 = pack_bf16x2_hi(v0.x - __bfloat162float(hh0.x),
                                         v0.y - __bfloat162float(hh0.y));
            uint32_t l1 = pack_bf16x2_hi(v0.z - __bfloat162float(hh1.x),
                                         v0.w - __bfloat162float(hh1.y));
            *(uint2*)&Ah[rr * 72 + c4 * 4] = make_uint2(h0, h1);
            *(uint2*)&Al[rr * 72 + c4 * 4] = make_uint2(l0, l1);
        }

        #pragma unroll
        for (int it = 0; it < 4; it++) {
            int idx = tid + 256 * it;
            int d   = idx >> 4;
            int n4  = idx & 15;
            float4 v0 = *(const float4*)&w[(size_t)(k0 + d) * HEAD + n4 * 4];
            float vals[4] = {v0.x, v0.y, v0.z, v0.w};
            #pragma unroll
            for (int j = 0; j < 4; j++) {
                __nv_bfloat16 h = __float2bfloat16(vals[j]);
                __nv_bfloat16 l = __float2bfloat16(vals[j] - __bfloat162float(h));
                Bh[(n4 * 4 + j) * 72 + d] = h;
                Bl[(n4 * 4 + j) * 72 + d] = l;
            }
        }
        __syncthreads();

        const int ar0 = (warp * 16 + g) * 72;
        const int ar1 = (warp * 16 + g + 8) * 72;
        #pragma unroll
        for (int ks = 0; ks < 4; ks++) {
            const int kb = ks * 16 + qd * 2;
            uint32_t ah[4], al[4];
            ah[0] = *(uint32_t*)&Ah[ar0 + kb];
            ah[1] = *(uint32_t*)&Ah[ar1 + kb];
            ah[2] = *(uint32_t*)&Ah[ar0 + kb + 8];
            ah[3] = *(uint32_t*)&Ah[ar1 + kb + 8];
            al[0] = *(uint32_t*)&Al[ar0 + kb];
            al[1] = *(uint32_t*)&Al[ar1 + kb];
            al[2] = *(uint32_t*)&Al[ar0 + kb + 8];
            al[3] = *(uint32_t*)&Al[ar1 + kb + 8];
            #pragma unroll
            for (int nt = 0; nt < 8; nt++) {
                const int br = (nt * 8 + g) * 72;
                uint32_t bh[2], bl[2];
                bh[0] = *(uint32_t*)&Bh[br + kb];
                bh[1] = *(uint32_t*)&Bh[br + kb + 8];
                bl[0] = *(uint32_t*)&Bl[br + kb];
                bl[1] = *(uint32_t*)&Bl[br + kb + 8];
                mma16816(acc[nt], ah, bh);
                mma16816(acc[nt], ah, bl);
                mma16816(acc[nt], al, bh);
            }
        }
    }

    const int r0 = row0 + warp * 16 + g;
    #pragma unroll
    for (int nt = 0; nt < 8; nt++) {
        const int col = nt * 8 + qd * 2;
        *(float2*)&out[(size_t)r0 * HEAD + col]       = make_float2(acc[nt][0], acc[nt][1]);
        *(float2*)&out[(size_t)(r0 + 8) * HEAD + col] = make_float2(acc[nt][2], acc[nt][3]);
    }
}

// ===========================================================================
// Kernel 2: split-KV causal flash attention via mma.sync bf16-split.
// Per block: 128 query rows x one KV chunk (<=16 tiles of 64 keys).
// 8 warps; warp w owns S/O rows [16w,16w+16) x full width (softmax in-warp).
// QK^T: Q,K hi/lo (3 terms). PV: P fragments reused in-register, hi/lo (3 terms).
// Grid.x enumerates (t, chunk): 8*1 + 8*2 + 8*3 + 8*4 = 80 per batch.
// ===========================================================================
// smem (73728 B): Qh[128][72] @0 | Ql @18432 | Kh[64][72] @36864 | Kl @46080
//                 Vh[64][72] @55296 | Vl @64512
#define ATTN_SMEM2 73728

__global__ __launch_bounds__(256) void attn_partial_mma()
{
    extern __shared__ char smem[];
    __nv_bfloat16* Qh = (__nv_bfloat16*)(smem);
    __nv_bfloat16* Ql = (__nv_bfloat16*)(smem + 18432);
    __nv_bfloat16* Kh = (__nv_bfloat16*)(smem + 36864);
    __nv_bfloat16* Kl = (__nv_bfloat16*)(smem + 46080);
    unsigned short* Vh = (unsigned short*)(smem + 55296);  // [key][head] bf16 bits
    unsigned short* Vl = (unsigned short*)(smem + 64512);

    const int b  = blockIdx.y;
    const int bx = blockIdx.x;
    int t, c;
    if      (bx <  8) { t = bx; c = 0; }
    else if (bx < 24) { int u = bx - 8;  t =  8 + (u >> 1); c = u & 1; }
    else if (bx < 48) { int u = bx - 24; t = 16 + u / 3;    c = u % 3; }
    else              { int u = bx - 48; t = 24 + (u >> 2); c = u & 3; }

    const int n_begin = c * 16;
    int n_end = 2 * t + 1;
    if (n_end > n_begin + 15) n_end = n_begin + 15;

    const int tid  = threadIdx.x;
    const int warp = tid >> 5;
    const int lane = tid & 31;
    const int g    = lane >> 2;
    const int qd   = lane & 3;
    const int qrow = t * 128 + warp * 16;

    const float* qh = g_qh + (size_t)b * SEQ * HEAD;
    const float* kh = g_kh + (size_t)b * SEQ * HEAD;
    const float* vh = g_vh + (size_t)b * SEQ * HEAD;

    // ---- stage Q (128x64 -> bf16 hi/lo) once ----
    #pragma unroll
    for (int it = 0; it < 8; it++) {
        int f  = tid + 256 * it;
        int rr = f >> 4;
        int c4 = f & 15;
        float4 v0 = *(const float4*)&qh[(size_t)(t * 128 + rr) * HEAD + c4 * 4];
        uint32_t h0 = pack_bf16x2_hi(v0.x, v0.y);
        uint32_t h1 = pack_bf16x2_hi(v0.z, v0.w);
        __nv_bfloat162 hh0 = *(__nv_bfloat162*)&h0;
        __nv_bfloat162 hh1 = *(__nv_bfloat162*)&h1;
        uint32_t l0 = pack_bf16x2_hi(v0.x - __bfloat162float(hh0.x),
                                     v0.y - __bfloat162float(hh0.y));
        uint32_t l1 = pack_bf16x2_hi(v0.z - __bfloat162float(hh1.x),
                                     v0.w - __bfloat162float(hh1.y));
        *(uint2*)&Qh[rr * 72 + c4 * 4] = make_uint2(h0, h1);
        *(uint2*)&Ql[rr * 72 + c4 * 4] = make_uint2(l0, l1);
    }

    float oa[8][4];
    #pragma unroll
    for (int nt = 0; nt < 8; nt++)
        #pragma unroll
        for (int i = 0; i < 4; i++) oa[nt][i] = 0.0f;
    float m0 = -1e30f, m1 = -1e30f, l0r = 0.0f, l1r = 0.0f;

    for (int n0 = n_begin; n0 <= n_end; n0++) {
        __syncthreads();   // previous iter's K/V reads done (also covers Q staging)

        // ---- stage K and V tiles [64x64] hi/lo (identical conflict-free pattern) ----
        #pragma unroll
        for (int it = 0; it < 4; it++) {
            int f  = tid + 256 * it;
            int rr = f >> 4;
            int c4 = f & 15;
            size_t gofs = (size_t)(n0 * 64 + rr) * HEAD + c4 * 4;
            float4 kv = *(const float4*)&kh[gofs];
            uint32_t h0 = pack_bf16x2_hi(kv.x, kv.y);
            uint32_t h1 = pack_bf16x2_hi(kv.z, kv.w);
            __nv_bfloat162 hh0 = *(__nv_bfloat162*)&h0;
            __nv_bfloat162 hh1 = *(__nv_bfloat162*)&h1;
            uint32_t l0 = pack_bf16x2_hi(kv.x - __bfloat162float(hh0.x),
                                         kv.y - __bfloat162float(hh0.y));
            uint32_t l1 = pack_bf16x2_hi(kv.z - __bfloat162float(hh1.x),
                                         kv.w - __bfloat162float(hh1.y));
            *(uint2*)&Kh[rr * 72 + c4 * 4] = make_uint2(h0, h1);
            *(uint2*)&Kl[rr * 72 + c4 * 4] = make_uint2(l0, l1);

            float4 vv = *(const float4*)&vh[gofs];
            uint32_t vh0 = pack_bf16x2_hi(vv.x, vv.y);
            uint32_t vh1 = pack_bf16x2_hi(vv.z, vv.w);
            __nv_bfloat162 vhh0 = *(__nv_bfloat162*)&vh0;
            __nv_bfloat162 vhh1 = *(__nv_bfloat162*)&vh1;
            uint32_t vl0 = pack_bf16x2_hi(vv.x - __bfloat162float(vhh0.x),
                                          vv.y - __bfloat162float(vhh0.y));
            uint32_t vl1 = pack_bf16x2_hi(vv.z - __bfloat162float(vhh1.x),
                                          vv.w - __bfloat162float(vhh1.y));
            *(uint2*)&Vh[rr * 72 + c4 * 4] = make_uint2(vh0, vh1);
            *(uint2*)&Vl[rr * 72 + c4 * 4] = make_uint2(vl0, vl1);
        }
        __syncthreads();

        // ---- S = Q K^T (3-term bf16 split) ----
        float s[8][4];
        #pragma unroll
        for (int nt = 0; nt < 8; nt++)
            #pragma unroll
            for (int i = 0; i < 4; i++) s[nt][i] = 0.0f;

        const int ar0 = (warp * 16 + g) * 72;
        const int ar1 = (warp * 16 + g + 8) * 72;
        #pragma unroll
        for (int ks = 0; ks < 4; ks++) {
            const int kb = ks * 16 + qd * 2;
            uint32_t ah[4], al[4];
            ah[0] = *(uint32_t*)&Qh[ar0 + kb];
            ah[1] = *(uint32_t*)&Qh[ar1 + kb];
            ah[2] = *(uint32_t*)&Qh[ar0 + kb + 8];
            ah[3] = *(uint32_t*)&Qh[ar1 + kb + 8];
            al[0] = *(uint32_t*)&Ql[ar0 + kb];
            al[1] = *(uint32_t*)&Ql[ar1 + kb];
            al[2] = *(uint32_t*)&Ql[ar0 + kb + 8];
            al[3] = *(uint32_t*)&Ql[ar1 + kb + 8];
            #pragma unroll
            for (int nt = 0; nt < 8; nt++) {
                const int br = (nt * 8 + g) * 72;
                uint32_t bh[2], bl[2];
                bh[0] = *(uint32_t*)&Kh[br + kb];
                bh[1] = *(uint32_t*)&Kh[br + kb + 8];
                bl[0] = *(uint32_t*)&Kl[br + kb];
                bl[1] = *(uint32_t*)&Kl[br + kb + 8];
                mma16816(s[nt], ah, bh);
                mma16816(s[nt], ah, bl);
                mma16816(s[nt], al, bh);
            }
        }

        // ---- scale + causal mask ----
        const float scale = 0.125f;   // 1/sqrt(64)
        const bool needm = (n0 * 64 + 63) > qrow;
        const int r0 = qrow + g, r1 = qrow + g + 8;
        #pragma unroll
        for (int nt = 0; nt < 8; nt++) {
            const int col0 = n0 * 64 + nt * 8 + qd * 2;
            s[nt][0] *= scale; s[nt][1] *= scale;
            s[nt][2] *= scale; s[nt][3] *= scale;
            if (needm) {
                if (col0     > r0) s[nt][0] = -1e30f;
                if (col0 + 1 > r0) s[nt][1] = -1e30f;
                if (col0     > r1) s[nt][2] = -1e30f;
                if (col0 + 1 > r1) s[nt][3] = -1e30f;
            }
        }

        // ---- online softmax (rows g, g+8; reduce across quad lanes) ----
        float mx0 = -1e30f, mx1 = -1e30f;
        #pragma unroll
        for (int nt = 0; nt < 8; nt++) {
            mx0 = fmaxf(mx0, fmaxf(s[nt][0], s[nt][1]));
            mx1 = fmaxf(mx1, fmaxf(s[nt][2], s[nt][3]));
        }
        mx0 = fmaxf(mx0, __shfl_xor_sync(0xffffffffu, mx0, 1));
        mx0 = fmaxf(mx0, __shfl_xor_sync(0xffffffffu, mx0, 2));
        mx1 = fmaxf(mx1, __shfl_xor_sync(0xffffffffu, mx1, 1));
        mx1 = fmaxf(mx1, __shfl_xor_sync(0xffffffffu, mx1, 2));
        const float mn0 = fmaxf(m0, mx0), mn1 = fmaxf(m1, mx1);
        const float corr0 = __expf(m0 - mn0), corr1 = __expf(m1 - mn1);
        m0 = mn0; m1 = mn1;

        float rs0 = 0.0f, rs1 = 0.0f;
        #pragma unroll
        for (int nt = 0; nt < 8; nt++) {
            s[nt][0] = __expf(s[nt][0] - mn0);
            s[nt][1] = __expf(s[nt][1] - mn0);
            s[nt][2] = __expf(s[nt][2] - mn1);
            s[nt][3] = __expf(s[nt][3] - mn1);
            rs0 += s[nt][0] + s[nt][1];
            rs1 += s[nt][2] + s[nt][3];
        }
        rs0 += __shfl_xor_sync(0xffffffffu, rs0, 1);
        rs0 += __shfl_xor_sync(0xffffffffu, rs0, 2);
        rs1 += __shfl_xor_sync(0xffffffffu, rs1, 1);
        rs1 += __shfl_xor_sync(0xffffffffu, rs1, 2);
        l0r = l0r * corr0 + rs0;
        l1r = l1r * corr1 + rs1;
        #pragma unroll
        for (int nt = 0; nt < 8; nt++) {
            oa[nt][0] *= corr0; oa[nt][1] *= corr0;
            oa[nt][2] *= corr1; oa[nt][3] *= corr1;
        }

        // ---- O += P V (P fragments built in-register, hi/lo split) ----
        #pragma unroll
        for (int kk = 0; kk < 4; kk++) {
            uint32_t pa[4], pl[4];
            {
                uint32_t h;
                __nv_bfloat162 hv;
                h = pack_bf16x2_hi(s[2*kk][0], s[2*kk][1]);   hv = *(__nv_bfloat162*)&h;
                pa[0] = h;
                pl[0] = pack_bf16x2_hi(s[2*kk][0] - __bfloat162float(hv.x),
                                       s[2*kk][1] - __bfloat162float(hv.y));
                h = pack_bf16x2_hi(s[2*kk][2], s[2*kk][3]);   hv = *(__nv_bfloat162*)&h;
                pa[1] = h;
                pl[1] = pack_bf16x2_hi(s[2*kk][2] - __bfloat162float(hv.x),
                                       s[2*kk][3] - __bfloat162float(hv.y));
                h = pack_bf16x2_hi(s[2*kk+1][0], s[2*kk+1][1]); hv = *(__nv_bfloat162*)&h;
                pa[2] = h;
                pl[2] = pack_bf16x2_hi(s[2*kk+1][0] - __bfloat162float(hv.x),
                                       s[2*kk+1][1] - __bfloat162float(hv.y));
                h = pack_bf16x2_hi(s[2*kk+1][2], s[2*kk+1][3]); hv = *(__nv_bfloat162*)&h;
                pa[3] = h;
                pl[3] = pack_bf16x2_hi(s[2*kk+1][2] - __bfloat162float(hv.x),
                                       s[2*kk+1][3] - __bfloat162float(hv.y));
            }
            const int kbase = kk * 16 + qd * 2;
            #pragma unroll
            for (int nt = 0; nt < 8; nt++) {
                const int ha = nt * 8 + g;
                uint32_t vbh[2], vbl[2];
                vbh[0] = (uint32_t)Vh[(kbase)     * 72 + ha] |
                         ((uint32_t)Vh[(kbase + 1) * 72 + ha] << 16);
                vbh[1] = (uint32_t)Vh[(kbase + 8) * 72 + ha] |
                         ((uint32_t)Vh[(kbase + 9) * 72 + ha] << 16);
                vbl[0] = (uint32_t)Vl[(kbase)     * 72 + ha] |
                         ((uint32_t)Vl[(kbase + 1) * 72 + ha] << 16);
                vbl[1] = (uint32_t)Vl[(kbase + 8) * 72 + ha] |
                         ((uint32_t)Vl[(kbase + 9) * 72 + ha] << 16);
                mma16816(oa[nt], pa, vbh);
                mma16816(oa[nt], pl, vbh);
                mma16816(oa[nt], pa, vbl);
            }
        }
    }

    // ---- epilogue: write unnormalized partial O and (m, l) ----
    const int slot = (b * QT2 + t) * MAXC + c;
    float* po = g_po + (size_t)slot * (128 * 64);
    const int orow0 = warp * 16 + g;
    #pragma unroll
    for (int nt = 0; nt < 8; nt++) {
        const int col = nt * 8 + qd * 2;
        *(float2*)&po[(orow0)     * 64 + col] = make_float2(oa[nt][0], oa[nt][1]);
        *(float2*)&po[(orow0 + 8) * 64 + col] = make_float2(oa[nt][2], oa[nt][3]);
    }
    if (qd == 0) {
        g_pm[slot * 128 + orow0]     = m0;
        g_pm[slot * 128 + orow0 + 8] = m1;
        g_pl[slot * 128 + orow0]     = l0r;
        g_pl[slot * 128 + orow0 + 8] = l1r;
    }
}

// ---------------------------------------------------------------------------
// Kernel 3: merge split-KV partials. One block per (t, b), 128 rows.
// ---------------------------------------------------------------------------
__global__ __launch_bounds__(256) void attn_merge_kernel(float* __restrict__ out)
{
    const int b  = blockIdx.y;
    const int t  = blockIdx.x;
    const int nc = (2 * t + 17) >> 4;   // ceil((2t+2)/16)

    const int tid = threadIdx.x;
    const int tx  = tid & 15;
    const int ty  = tid >> 4;

    const int slot0 = (b * QT2 + t) * MAXC;

    #pragma unroll
    for (int i = 0; i < 8; i++) {
        const int r = ty * 8 + i;
        float M = -1e30f;
        for (int c = 0; c < nc; c++)
            M = fmaxf(M, g_pm[(slot0 + c) * 128 + r]);
        float L = 0.0f;
        float w[MAXC];
        for (int c = 0; c < nc; c++) {
            w[c] = __expf(g_pm[(slot0 + c) * 128 + r] - M);
            L += w[c] * g_pl[(slot0 + c) * 128 + r];
        }
        float4 acc = make_float4(0.f, 0.f, 0.f, 0.f);
        for (int c = 0; c < nc; c++) {
            const float4 v = *(const float4*)&g_po[(size_t)(slot0 + c) * (128 * 64) + r * 64 + tx * 4];
            acc.x += w[c] * v.x; acc.y += w[c] * v.y;
            acc.z += w[c] * v.z; acc.w += w[c] * v.w;
        }
        const float inv = 1.0f / L;
        acc.x *= inv; acc.y *= inv; acc.z *= inv; acc.w *= inv;
        *(float4*)&out[((size_t)b * SEQ + t * 128 + r) * HEAD + tx * 4] = acc;
    }
}

// ---------------------------------------------------------------------------
extern "C" void kernel_launch(void* const* d_in, const int* in_sizes, int n_in,
                              void* d_out, int out_size)
{
    const float* q  = (const float*)d_in[0];
    const float* k  = (const float*)d_in[1];
    const float* v  = (const float*)d_in[2];
    const float* wq = (const float*)d_in[3];
    const float* wk = (const float*)d_in[4];
    const float* wv = (const float*)d_in[5];
    float* out = (float*)d_out;

    cudaFuncSetAttribute(proj_mma_kernel, cudaFuncAttributeMaxDynamicSharedMemorySize, PROJ_SMEM);
    cudaFuncSetAttribute(attn_partial_mma, cudaFuncAttributeMaxDynamicSharedMemorySize, ATTN_SMEM2);

    // mma.sync projections: 128-row tiles, grid.z selects q/k/v
    proj_mma_kernel<<<dim3((BATCH * SEQ) / 128, 1, 3), 256, PROJ_SMEM>>>(q, k, v, wq, wk, wv);

    // mma.sync split-KV partials: 80 (t,chunk) pairs per batch
    attn_partial_mma<<<dim3(80, BATCH), 256, ATTN_SMEM2>>>();

    // merge: one block per 128-row query tile per batch
    attn_merge_kernel<<<dim3(QT2, BATCH), 256>>>(out);
}

// round 15
// speedup vs baseline: 3.5389x; 1.0463x over previous
#include <cuda_runtime.h>
#include <cuda_bf16.h>
#include <cstdint>

// Problem constants
#define BATCH   4
#define SEQ     4096
#define DMODEL  1024
#define HEAD    64
#define QT2     32          // SEQ / 128 query tiles per batch (mma attention)
#define NTILES  64
#define MAXC    4

// Scratch for projected q/k/v heads: [B, S, H] fp32 each (4 MB each)
__device__ float g_qh[BATCH * SEQ * HEAD];
__device__ float g_kh[BATCH * SEQ * HEAD];
__device__ float g_vh[BATCH * SEQ * HEAD];

// Split-KV partials (128-row tiles): O unnorm [b][t][c][128][64], m/l [b][t][c][128]
__device__ float g_po[(size_t)BATCH * NTILES * MAXC * 64 * 64];
__device__ float g_pm[BATCH * NTILES * MAXC * 64];
__device__ float g_pl[BATCH * NTILES * MAXC * 64];

// ---------------------------------------------------------------------------
// mma.sync m16n8k16 bf16 -> f32 (baseline PTX, works on plain sm_103 target)
// ---------------------------------------------------------------------------
__device__ __forceinline__ void mma16816(float* c, const uint32_t* a, const uint32_t* b) {
    asm volatile(
        "mma.sync.aligned.m16n8k16.row.col.f32.bf16.bf16.f32 "
        "{%0,%1,%2,%3}, {%4,%5,%6,%7}, {%8,%9}, {%0,%1,%2,%3};"
        : "+f"(c[0]), "+f"(c[1]), "+f"(c[2]), "+f"(c[3])
        : "r"(a[0]), "r"(a[1]), "r"(a[2]), "r"(a[3]), "r"(b[0]), "r"(b[1]));
}

__device__ __forceinline__ uint32_t pack_bf16x2_hi(float a, float b) {
    __nv_bfloat162 h = __floats2bfloat162_rn(a, b);
    return *(uint32_t*)&h;
}

// ===========================================================================
// Kernel 1: mma.sync bf16-split projections, software-pipelined.
// D[128,64] = X[128,1024] @ W[1024,64]; prefetch chunk c+1 LDG during MMA of c.
// ===========================================================================
#define PROJ_SMEM 55296

__global__ __launch_bounds__(256, 2) void proj_mma_kernel(
    const float* __restrict__ q, const float* __restrict__ k, const float* __restrict__ v,
    const float* __restrict__ wq, const float* __restrict__ wk, const float* __restrict__ wv)
{
    extern __shared__ char smem[];
    __nv_bfloat16* Ah = (__nv_bfloat16*)(smem);
    __nv_bfloat16* Al = (__nv_bfloat16*)(smem + 18432);
    __nv_bfloat16* Bh = (__nv_bfloat16*)(smem + 36864);
    __nv_bfloat16* Bl = (__nv_bfloat16*)(smem + 46080);

    const int z = blockIdx.z;
    const float* x = (z == 0) ? q : (z == 1) ? k : v;
    const float* w = (z == 0) ? wq : (z == 1) ? wk : wv;
    float* out     = (z == 0) ? g_qh : (z == 1) ? g_kh : g_vh;

    const int row0 = blockIdx.x * 128;
    const int tid  = threadIdx.x;
    const int warp = tid >> 5;
    const int lane = tid & 31;
    const int g    = lane >> 2;
    const int qd   = lane & 3;

    float acc[8][4];
    #pragma unroll
    for (int nt = 0; nt < 8; nt++)
        #pragma unroll
        for (int i = 0; i < 4; i++) acc[nt][i] = 0.0f;

    // prefetch chunk 0
    float4 pA[8], pB[4];
    #pragma unroll
    for (int it = 0; it < 8; it++) {
        int f = tid + 256 * it, rr = f >> 4, c4 = f & 15;
        pA[it] = *(const float4*)&x[(size_t)(row0 + rr) * DMODEL + c4 * 4];
    }
    #pragma unroll
    for (int it = 0; it < 4; it++) {
        int idx = tid + 256 * it, d = idx >> 4, n4 = idx & 15;
        pB[it] = *(const float4*)&w[(size_t)d * HEAD + n4 * 4];
    }

    for (int c = 0; c < 16; c++) {
        // ---- convert + STS staged chunk ----
        #pragma unroll
        for (int it = 0; it < 8; it++) {
            int f  = tid + 256 * it, rr = f >> 4, c4 = f & 15;
            float4 v0 = pA[it];
            uint32_t h0 = pack_bf16x2_hi(v0.x, v0.y);
            uint32_t h1 = pack_bf16x2_hi(v0.z, v0.w);
            __nv_bfloat162 hh0 = *(__nv_bfloat162*)&h0;
            __nv_bfloat162 hh1 = *(__nv_bfloat162*)&h1;
            uint32_t l0 = pack_bf16x2_hi(v0.x - __bfloat162float(hh0.x),
                                         v0.y - __bfloat162float(hh0.y));
            uint32_t l1 = pack_bf16x2_hi(v0.z - __bfloat162float(hh1.x),
                                         v0.w - __bfloat162float(hh1.y));
            *(uint2*)&Ah[rr * 72 + c4 * 4] = make_uint2(h0, h1);
            *(uint2*)&Al[rr * 72 + c4 * 4] = make_uint2(l0, l1);
        }
        #pragma unroll
        for (int it = 0; it < 4; it++) {
            int idx = tid + 256 * it, d = idx >> 4, n4 = idx & 15;
            float4 v0 = pB[it];
            float vals[4] = {v0.x, v0.y, v0.z, v0.w};
            #pragma unroll
            for (int j = 0; j < 4; j++) {
                __nv_bfloat16 h = __float2bfloat16(vals[j]);
                __nv_bfloat16 l = __float2bfloat16(vals[j] - __bfloat162float(h));
                Bh[(n4 * 4 + j) * 72 + d] = h;
                Bl[(n4 * 4 + j) * 72 + d] = l;
            }
        }
        __syncthreads();

        // ---- prefetch next chunk (LDG latency hidden behind MMA phase) ----
        if (c < 15) {
            const int k1 = (c + 1) * 64;
            #pragma unroll
            for (int it = 0; it < 8; it++) {
                int f = tid + 256 * it, rr = f >> 4, c4 = f & 15;
                pA[it] = *(const float4*)&x[(size_t)(row0 + rr) * DMODEL + k1 + c4 * 4];
            }
            #pragma unroll
            for (int it = 0; it < 4; it++) {
                int idx = tid + 256 * it, d = idx >> 4, n4 = idx & 15;
                pB[it] = *(const float4*)&w[(size_t)(k1 + d) * HEAD + n4 * 4];
            }
        }

        // ---- MMA: 4 k-steps x 8 n-tiles x 3 pairings ----
        const int ar0 = (warp * 16 + g) * 72;
        const int ar1 = (warp * 16 + g + 8) * 72;
        #pragma unroll
        for (int ks = 0; ks < 4; ks++) {
            const int kb = ks * 16 + qd * 2;
            uint32_t ah[4], al[4];
            ah[0] = *(uint32_t*)&Ah[ar0 + kb];
            ah[1] = *(uint32_t*)&Ah[ar1 + kb];
            ah[2] = *(uint32_t*)&Ah[ar0 + kb + 8];
            ah[3] = *(uint32_t*)&Ah[ar1 + kb + 8];
            al[0] = *(uint32_t*)&Al[ar0 + kb];
            al[1] = *(uint32_t*)&Al[ar1 + kb];
            al[2] = *(uint32_t*)&Al[ar0 + kb + 8];
            al[3] = *(uint32_t*)&Al[ar1 + kb + 8];
            #pragma unroll
            for (int nt = 0; nt < 8; nt++) {
                const int br = (nt * 8 + g) * 72;
                uint32_t bh[2], bl[2];
                bh[0] = *(uint32_t*)&Bh[br + kb];
                bh[1] = *(uint32_t*)&Bh[br + kb + 8];
                bl[0] = *(uint32_t*)&Bl[br + kb];
                bl[1] = *(uint32_t*)&Bl[br + kb + 8];
                mma16816(acc[nt], ah, bh);
                mma16816(acc[nt], ah, bl);
                mma16816(acc[nt], al, bh);
            }
        }
        __syncthreads();   // MMA smem reads done before next STS
    }

    const int r0 = row0 + warp * 16 + g;
    #pragma unroll
    for (int nt = 0; nt < 8; nt++) {
        const int col = nt * 8 + qd * 2;
        *(float2*)&out[(size_t)r0 * HEAD + col]       = make_float2(acc[nt][0], acc[nt][1]);
        *(float2*)&out[(size_t)(r0 + 8) * HEAD + col] = make_float2(acc[nt][2], acc[nt][3]);
    }
}

// ===========================================================================
// Kernel 2: split-KV causal flash attention via mma.sync, software-pipelined.
// Per block: 128 query rows x one KV chunk (<=16 tiles of 64 keys).
// ===========================================================================
#define ATTN_SMEM2 73728

__global__ __launch_bounds__(256, 2) void attn_partial_mma()
{
    extern __shared__ char smem[];
    __nv_bfloat16* Qh = (__nv_bfloat16*)(smem);
    __nv_bfloat16* Ql = (__nv_bfloat16*)(smem + 18432);
    __nv_bfloat16* Kh = (__nv_bfloat16*)(smem + 36864);
    __nv_bfloat16* Kl = (__nv_bfloat16*)(smem + 46080);
    unsigned short* Vh = (unsigned short*)(smem + 55296);  // [key][head] bf16 bits
    unsigned short* Vl = (unsigned short*)(smem + 64512);

    const int b  = blockIdx.y;
    const int bx = blockIdx.x;
    int t, c;
    if      (bx <  8) { t = bx; c = 0; }
    else if (bx < 24) { int u = bx - 8;  t =  8 + (u >> 1); c = u & 1; }
    else if (bx < 48) { int u = bx - 24; t = 16 + u / 3;    c = u % 3; }
    else              { int u = bx - 48; t = 24 + (u >> 2); c = u & 3; }

    const int n_begin = c * 16;
    int n_end = 2 * t + 1;
    if (n_end > n_begin + 15) n_end = n_begin + 15;

    const int tid  = threadIdx.x;
    const int warp = tid >> 5;
    const int lane = tid & 31;
    const int g    = lane >> 2;
    const int qd   = lane & 3;
    const int qrow = t * 128 + warp * 16;

    const float* qh = g_qh + (size_t)b * SEQ * HEAD;
    const float* kh = g_kh + (size_t)b * SEQ * HEAD;
    const float* vh = g_vh + (size_t)b * SEQ * HEAD;

    // ---- stage Q (128x64 -> bf16 hi/lo) once ----
    #pragma unroll
    for (int it = 0; it < 8; it++) {
        int f  = tid + 256 * it, rr = f >> 4, c4 = f & 15;
        float4 v0 = *(const float4*)&qh[(size_t)(t * 128 + rr) * HEAD + c4 * 4];
        uint32_t h0 = pack_bf16x2_hi(v0.x, v0.y);
        uint32_t h1 = pack_bf16x2_hi(v0.z, v0.w);
        __nv_bfloat162 hh0 = *(__nv_bfloat162*)&h0;
        __nv_bfloat162 hh1 = *(__nv_bfloat162*)&h1;
        uint32_t l0 = pack_bf16x2_hi(v0.x - __bfloat162float(hh0.x),
                                     v0.y - __bfloat162float(hh0.y));
        uint32_t l1 = pack_bf16x2_hi(v0.z - __bfloat162float(hh1.x),
                                     v0.w - __bfloat162float(hh1.y));
        *(uint2*)&Qh[rr * 72 + c4 * 4] = make_uint2(h0, h1);
        *(uint2*)&Ql[rr * 72 + c4 * 4] = make_uint2(l0, l1);
    }

    // prefetch first K/V tile
    float4 pK[4], pV[4];
    #pragma unroll
    for (int it = 0; it < 4; it++) {
        int f = tid + 256 * it, rr = f >> 4, c4 = f & 15;
        size_t gofs = (size_t)(n_begin * 64 + rr) * HEAD + c4 * 4;
        pK[it] = *(const float4*)&kh[gofs];
        pV[it] = *(const float4*)&vh[gofs];
    }

    float oa[8][4];
    #pragma unroll
    for (int nt = 0; nt < 8; nt++)
        #pragma unroll
        for (int i = 0; i < 4; i++) oa[nt][i] = 0.0f;
    float m0 = -1e30f, m1 = -1e30f, l0r = 0.0f, l1r = 0.0f;

    for (int n0 = n_begin; n0 <= n_end; n0++) {
        // ---- convert + STS K/V from prefetch regs ----
        #pragma unroll
        for (int it = 0; it < 4; it++) {
            int f  = tid + 256 * it, rr = f >> 4, c4 = f & 15;
            float4 kv = pK[it];
            uint32_t h0 = pack_bf16x2_hi(kv.x, kv.y);
            uint32_t h1 = pack_bf16x2_hi(kv.z, kv.w);
            __nv_bfloat162 hh0 = *(__nv_bfloat162*)&h0;
            __nv_bfloat162 hh1 = *(__nv_bfloat162*)&h1;
            uint32_t l0 = pack_bf16x2_hi(kv.x - __bfloat162float(hh0.x),
                                         kv.y - __bfloat162float(hh0.y));
            uint32_t l1 = pack_bf16x2_hi(kv.z - __bfloat162float(hh1.x),
                                         kv.w - __bfloat162float(hh1.y));
            *(uint2*)&Kh[rr * 72 + c4 * 4] = make_uint2(h0, h1);
            *(uint2*)&Kl[rr * 72 + c4 * 4] = make_uint2(l0, l1);

            float4 vv = pV[it];
            uint32_t vh0 = pack_bf16x2_hi(vv.x, vv.y);
            uint32_t vh1 = pack_bf16x2_hi(vv.z, vv.w);
            __nv_bfloat162 vhh0 = *(__nv_bfloat162*)&vh0;
            __nv_bfloat162 vhh1 = *(__nv_bfloat162*)&vh1;
            uint32_t vl0 = pack_bf16x2_hi(vv.x - __bfloat162float(vhh0.x),
                                          vv.y - __bfloat162float(vhh0.y));
            uint32_t vl1 = pack_bf16x2_hi(vv.z - __bfloat162float(vhh1.x),
                                          vv.w - __bfloat162float(vhh1.y));
            *(uint2*)&Vh[rr * 72 + c4 * 4] = make_uint2(vh0, vh1);
            *(uint2*)&Vl[rr * 72 + c4 * 4] = make_uint2(vl0, vl1);
        }
        __syncthreads();   // K/V (and Q on first iter) visible to all warps

        // ---- prefetch next K/V tile ----
        if (n0 < n_end) {
            #pragma unroll
            for (int it = 0; it < 4; it++) {
                int f = tid + 256 * it, rr = f >> 4, c4 = f & 15;
                size_t gofs = (size_t)((n0 + 1) * 64 + rr) * HEAD + c4 * 4;
                pK[it] = *(const float4*)&kh[gofs];
                pV[it] = *(const float4*)&vh[gofs];
            }
        }

        // ---- S = Q K^T (3-term bf16 split) ----
        float s[8][4];
        #pragma unroll
        for (int nt = 0; nt < 8; nt++)
            #pragma unroll
            for (int i = 0; i < 4; i++) s[nt][i] = 0.0f;

        const int ar0 = (warp * 16 + g) * 72;
        const int ar1 = (warp * 16 + g + 8) * 72;
        #pragma unroll
        for (int ks = 0; ks < 4; ks++) {
            const int kb = ks * 16 + qd * 2;
            uint32_t ah[4], al[4];
            ah[0] = *(uint32_t*)&Qh[ar0 + kb];
            ah[1] = *(uint32_t*)&Qh[ar1 + kb];
            ah[2] = *(uint32_t*)&Qh[ar0 + kb + 8];
            ah[3] = *(uint32_t*)&Qh[ar1 + kb + 8];
            al[0] = *(uint32_t*)&Ql[ar0 + kb];
            al[1] = *(uint32_t*)&Ql[ar1 + kb];
            al[2] = *(uint32_t*)&Ql[ar0 + kb + 8];
            al[3] = *(uint32_t*)&Ql[ar1 + kb + 8];
            #pragma unroll
            for (int nt = 0; nt < 8; nt++) {
                const int br = (nt * 8 + g) * 72;
                uint32_t bh[2], bl[2];
                bh[0] = *(uint32_t*)&Kh[br + kb];
                bh[1] = *(uint32_t*)&Kh[br + kb + 8];
                bl[0] = *(uint32_t*)&Kl[br + kb];
                bl[1] = *(uint32_t*)&Kl[br + kb + 8];
                mma16816(s[nt], ah, bh);
                mma16816(s[nt], ah, bl);
                mma16816(s[nt], al, bh);
            }
        }

        // ---- scale + causal mask ----
        const float scale = 0.125f;   // 1/sqrt(64)
        const bool needm = (n0 * 64 + 63) > qrow;
        const int r0 = qrow + g, r1 = qrow + g + 8;
        #pragma unroll
        for (int nt = 0; nt < 8; nt++) {
            const int col0 = n0 * 64 + nt * 8 + qd * 2;
            s[nt][0] *= scale; s[nt][1] *= scale;
            s[nt][2] *= scale; s[nt][3] *= scale;
            if (needm) {
                if (col0     > r0) s[nt][0] = -1e30f;
                if (col0 + 1 > r0) s[nt][1] = -1e30f;
                if (col0     > r1) s[nt][2] = -1e30f;
                if (col0 + 1 > r1) s[nt][3] = -1e30f;
            }
        }

        // ---- online softmax (rows g, g+8; reduce across quad lanes) ----
        float mx0 = -1e30f, mx1 = -1e30f;
        #pragma unroll
        for (int nt = 0; nt < 8; nt++) {
            mx0 = fmaxf(mx0, fmaxf(s[nt][0], s[nt][1]));
            mx1 = fmaxf(mx1, fmaxf(s[nt][2], s[nt][3]));
        }
        mx0 = fmaxf(mx0, __shfl_xor_sync(0xffffffffu, mx0, 1));
        mx0 = fmaxf(mx0, __shfl_xor_sync(0xffffffffu, mx0, 2));
        mx1 = fmaxf(mx1, __shfl_xor_sync(0xffffffffu, mx1, 1));
        mx1 = fmaxf(mx1, __shfl_xor_sync(0xffffffffu, mx1, 2));
        const float mn0 = fmaxf(m0, mx0), mn1 = fmaxf(m1, mx1);
        const float corr0 = __expf(m0 - mn0), corr1 = __expf(m1 - mn1);
        m0 = mn0; m1 = mn1;

        float rs0 = 0.0f, rs1 = 0.0f;
        #pragma unroll
        for (int nt = 0; nt < 8; nt++) {
            s[nt][0] = __expf(s[nt][0] - mn0);
            s[nt][1] = __expf(s[nt][1] - mn0);
            s[nt][2] = __expf(s[nt][2] - mn1);
            s[nt][3] = __expf(s[nt][3] - mn1);
            rs0 += s[nt][0] + s[nt][1];
            rs1 += s[nt][2] + s[nt][3];
        }
        rs0 += __shfl_xor_sync(0xffffffffu, rs0, 1);
        rs0 += __shfl_xor_sync(0xffffffffu, rs0, 2);
        rs1 += __shfl_xor_sync(0xffffffffu, rs1, 1);
        rs1 += __shfl_xor_sync(0xffffffffu, rs1, 2);
        l0r = l0r * corr0 + rs0;
        l1r = l1r * corr1 + rs1;
        #pragma unroll
        for (int nt = 0; nt < 8; nt++) {
            oa[nt][0] *= corr0; oa[nt][1] *= corr0;
            oa[nt][2] *= corr1; oa[nt][3] *= corr1;
        }

        // ---- O += P V (P fragments built in-register, hi/lo split) ----
        #pragma unroll
        for (int kk = 0; kk < 4; kk++) {
            uint32_t pa[4], pl[4];
            {
                uint32_t h;
                __nv_bfloat162 hv;
                h = pack_bf16x2_hi(s[2*kk][0], s[2*kk][1]);   hv = *(__nv_bfloat162*)&h;
                pa[0] = h;
                pl[0] = pack_bf16x2_hi(s[2*kk][0] - __bfloat162float(hv.x),
                                       s[2*kk][1] - __bfloat162float(hv.y));
                h = pack_bf16x2_hi(s[2*kk][2], s[2*kk][3]);   hv = *(__nv_bfloat162*)&h;
                pa[1] = h;
                pl[1] = pack_bf16x2_hi(s[2*kk][2] - __bfloat162float(hv.x),
                                       s[2*kk][3] - __bfloat162float(hv.y));
                h = pack_bf16x2_hi(s[2*kk+1][0], s[2*kk+1][1]); hv = *(__nv_bfloat162*)&h;
                pa[2] = h;
                pl[2] = pack_bf16x2_hi(s[2*kk+1][0] - __bfloat162float(hv.x),
                                       s[2*kk+1][1] - __bfloat162float(hv.y));
                h = pack_bf16x2_hi(s[2*kk+1][2], s[2*kk+1][3]); hv = *(__nv_bfloat162*)&h;
                pa[3] = h;
                pl[3] = pack_bf16x2_hi(s[2*kk+1][2] - __bfloat162float(hv.x),
                                       s[2*kk+1][3] - __bfloat162float(hv.y));
            }
            const int kbase = kk * 16 + qd * 2;
            #pragma unroll
            for (int nt = 0; nt < 8; nt++) {
                const int ha = nt * 8 + g;
                uint32_t vbh[2], vbl[2];
                vbh[0] = (uint32_t)Vh[(kbase)     * 72 + ha] |
                         ((uint32_t)Vh[(kbase + 1) * 72 + ha] << 16);
                vbh[1] = (uint32_t)Vh[(kbase + 8) * 72 + ha] |
                         ((uint32_t)Vh[(kbase + 9) * 72 + ha] << 16);
                vbl[0] = (uint32_t)Vl[(kbase)     * 72 + ha] |
                         ((uint32_t)Vl[(kbase + 1) * 72 + ha] << 16);
                vbl[1] = (uint32_t)Vl[(kbase + 8) * 72 + ha] |
                         ((uint32_t)Vl[(kbase + 9) * 72 + ha] << 16);
                mma16816(oa[nt], pa, vbh);
                mma16816(oa[nt], pl, vbh);
                mma16816(oa[nt], pa, vbl);
            }
        }
        __syncthreads();   // smem reads done before next iter's STS
    }

    // ---- epilogue: write unnormalized partial O and (m, l) ----
    const int slot = (b * QT2 + t) * MAXC + c;
    float* po = g_po + (size_t)slot * (128 * 64);
    const int orow0 = warp * 16 + g;
    #pragma unroll
    for (int nt = 0; nt < 8; nt++) {
        const int col = nt * 8 + qd * 2;
        *(float2*)&po[(orow0)     * 64 + col] = make_float2(oa[nt][0], oa[nt][1]);
        *(float2*)&po[(orow0 + 8) * 64 + col] = make_float2(oa[nt][2], oa[nt][3]);
    }
    if (qd == 0) {
        g_pm[slot * 128 + orow0]     = m0;
        g_pm[slot * 128 + orow0 + 8] = m1;
        g_pl[slot * 128 + orow0]     = l0r;
        g_pl[slot * 128 + orow0 + 8] = l1r;
    }
}

// ---------------------------------------------------------------------------
// Kernel 3: merge split-KV partials. One block per (t, b), 128 rows.
// ---------------------------------------------------------------------------
__global__ __launch_bounds__(256) void attn_merge_kernel(float* __restrict__ out)
{
    const int b  = blockIdx.y;
    const int t  = blockIdx.x;
    const int nc = (2 * t + 17) >> 4;   // ceil((2t+2)/16)

    const int tid = threadIdx.x;
    const int tx  = tid & 15;
    const int ty  = tid >> 4;

    const int slot0 = (b * QT2 + t) * MAXC;

    #pragma unroll
    for (int i = 0; i < 8; i++) {
        const int r = ty * 8 + i;
        float M = -1e30f;
        for (int c = 0; c < nc; c++)
            M = fmaxf(M, g_pm[(slot0 + c) * 128 + r]);
        float L = 0.0f;
        float w[MAXC];
        for (int c = 0; c < nc; c++) {
            w[c] = __expf(g_pm[(slot0 + c) * 128 + r] - M);
            L += w[c] * g_pl[(slot0 + c) * 128 + r];
        }
        float4 acc = make_float4(0.f, 0.f, 0.f, 0.f);
        for (int c = 0; c < nc; c++) {
            const float4 v = *(const float4*)&g_po[(size_t)(slot0 + c) * (128 * 64) + r * 64 + tx * 4];
            acc.x += w[c] * v.x; acc.y += w[c] * v.y;
            acc.z += w[c] * v.z; acc.w += w[c] * v.w;
        }
        const float inv = 1.0f / L;
        acc.x *= inv; acc.y *= inv; acc.z *= inv; acc.w *= inv;
        *(float4*)&out[((size_t)b * SEQ + t * 128 + r) * HEAD + tx * 4] = acc;
    }
}

// ---------------------------------------------------------------------------
extern "C" void kernel_launch(void* const* d_in, const int* in_sizes, int n_in,
                              void* d_out, int out_size)
{
    const float* q  = (const float*)d_in[0];
    const float* k  = (const float*)d_in[1];
    const float* v  = (const float*)d_in[2];
    const float* wq = (const float*)d_in[3];
    const float* wk = (const float*)d_in[4];
    const float* wv = (const float*)d_in[5];
    float* out = (float*)d_out;

    cudaFuncSetAttribute(proj_mma_kernel, cudaFuncAttributeMaxDynamicSharedMemorySize, PROJ_SMEM);
    cudaFuncSetAttribute(attn_partial_mma, cudaFuncAttributeMaxDynamicSharedMemorySize, ATTN_SMEM2);

    // mma.sync projections: 128-row tiles, grid.z selects q/k/v
    proj_mma_kernel<<<dim3((BATCH * SEQ) / 128, 1, 3), 256, PROJ_SMEM>>>(q, k, v, wq, wk, wv);

    // mma.sync split-KV partials: 80 (t,chunk) pairs per batch
    attn_partial_mma<<<dim3(80, BATCH), 256, ATTN_SMEM2>>>();

    // merge: one block per 128-row query tile per batch
    attn_merge_kernel<<<dim3(QT2, BATCH), 256>>>(out);
}

// round 16
// speedup vs baseline: 4.7107x; 1.3311x over previous
#include <cuda_runtime.h>
#include <cuda_bf16.h>
#include <cstdint>

// Problem constants
#define BATCH   4
#define SEQ     4096
#define DMODEL  1024
#define HEAD    64
#define QT2     32          // SEQ / 128 query tiles per batch (mma attention)
#define NTILES  64
#define MAXC    4

// Projected heads as bf16 hi/lo pairs (written by proj, read by attention)
#define NELEM (BATCH * SEQ * HEAD)
__device__ __align__(16) __nv_bfloat16 g_qhi[NELEM], g_qlo[NELEM];
__device__ __align__(16) __nv_bfloat16 g_khi[NELEM], g_klo[NELEM];
__device__ __align__(16) __nv_bfloat16 g_vhi[NELEM], g_vlo[NELEM];

// W transposed bf16 hi/lo: [z][n][k]
__device__ __align__(16) __nv_bfloat16 g_wthi[3 * HEAD * DMODEL];
__device__ __align__(16) __nv_bfloat16 g_wtlo[3 * HEAD * DMODEL];

// Split-KV partials (128-row tiles): O unnorm [b][t][c][128][64], m/l [b][t][c][128]
__device__ float g_po[(size_t)BATCH * NTILES * MAXC * 64 * 64];
__device__ float g_pm[BATCH * NTILES * MAXC * 64];
__device__ float g_pl[BATCH * NTILES * MAXC * 64];

// ---------------------------------------------------------------------------
// PTX helpers (all baseline ISA, valid on plain sm_103 target)
// ---------------------------------------------------------------------------
__device__ __forceinline__ void mma16816(float* c, const uint32_t* a, const uint32_t* b) {
    asm volatile(
        "mma.sync.aligned.m16n8k16.row.col.f32.bf16.bf16.f32 "
        "{%0,%1,%2,%3}, {%4,%5,%6,%7}, {%8,%9}, {%0,%1,%2,%3};"
        : "+f"(c[0]), "+f"(c[1]), "+f"(c[2]), "+f"(c[3])
        : "r"(a[0]), "r"(a[1]), "r"(a[2]), "r"(a[3]), "r"(b[0]), "r"(b[1]));
}

__device__ __forceinline__ uint32_t pack_bf16x2_hi(float a, float b) {
    __nv_bfloat162 h = __floats2bfloat162_rn(a, b);
    return *(uint32_t*)&h;
}

__device__ __forceinline__ uint32_t smem_u32(const void* p) {
    uint32_t a;
    asm("{ .reg .u64 t; cvta.to.shared.u64 t, %1; cvt.u32.u64 %0, t; }"
        : "=r"(a) : "l"(p));
    return a;
}

#define CP16(dst_u32, src_ptr) \
    asm volatile("cp.async.cg.shared.global [%0], [%1], 16;" \
                 :: "r"(dst_u32), "l"(src_ptr))
#define CP_COMMIT() asm volatile("cp.async.commit_group;" ::: "memory")
#define CP_WAIT0()  asm volatile("cp.async.wait_group 0;" ::: "memory")

// ===========================================================================
// Kernel 0: one-time W -> transposed bf16 hi/lo.  wt[z][n][k] = w[z][k][n]
// ===========================================================================
__global__ __launch_bounds__(256) void conv_w_kernel(
    const float* __restrict__ wq, const float* __restrict__ wk, const float* __restrict__ wv)
{
    const int z = blockIdx.y;
    const float* w = (z == 0) ? wq : (z == 1) ? wk : wv;
    __nv_bfloat16* oh = g_wthi + (size_t)z * HEAD * DMODEL;
    __nv_bfloat16* ol = g_wtlo + (size_t)z * HEAD * DMODEL;

    const int idx = blockIdx.x * 256 + threadIdx.x;   // 0..16383 over (k, n4)
    const int k  = idx >> 4;
    const int n4 = idx & 15;
    float4 v = *(const float4*)&w[(size_t)k * HEAD + n4 * 4];
    float vals[4] = {v.x, v.y, v.z, v.w};
    #pragma unroll
    for (int j = 0; j < 4; j++) {
        __nv_bfloat16 h = __float2bfloat16(vals[j]);
        __nv_bfloat16 l = __float2bfloat16(vals[j] - __bfloat162float(h));
        oh[(size_t)(n4 * 4 + j) * DMODEL + k] = h;
        ol[(size_t)(n4 * 4 + j) * DMODEL + k] = l;
    }
}

// ===========================================================================
// Kernel 1: mma.sync bf16-split projections.
// A: fp32 X staged via register prefetch + cvt (unavoidable, each elem once).
// B: pre-converted bf16 hi/lo via cp.async, double-buffered.
// Output: bf16 hi/lo pairs straight to gmem.
// ===========================================================================
// smem: Ah[128][72]bf16 @0 | Al @18432 | Bbuf{0,1} @36864+buf*18432 {Bh, Bl@+9216}
#define PROJ_SMEM 73728

__global__ __launch_bounds__(256, 2) void proj_mma_kernel(
    const float* __restrict__ q, const float* __restrict__ k, const float* __restrict__ v)
{
    extern __shared__ char smem[];
    const uint32_t sb = smem_u32(smem);
    __nv_bfloat16* Ah = (__nv_bfloat16*)(smem);
    __nv_bfloat16* Al = (__nv_bfloat16*)(smem + 18432);

    const int z = blockIdx.z;
    const float* x = (z == 0) ? q : (z == 1) ? k : v;
    const __nv_bfloat16* whi = g_wthi + (size_t)z * HEAD * DMODEL;
    const __nv_bfloat16* wlo = g_wtlo + (size_t)z * HEAD * DMODEL;
    __nv_bfloat16* ohi = (z == 0) ? g_qhi : (z == 1) ? g_khi : g_vhi;
    __nv_bfloat16* olo = (z == 0) ? g_qlo : (z == 1) ? g_klo : g_vlo;

    const int row0 = blockIdx.x * 128;
    const int tid  = threadIdx.x;
    const int warp = tid >> 5;
    const int lane = tid & 31;
    const int g    = lane >> 2;
    const int qd   = lane & 3;

    float acc[8][4];
    #pragma unroll
    for (int nt = 0; nt < 8; nt++)
        #pragma unroll
        for (int i = 0; i < 4; i++) acc[nt][i] = 0.0f;

    // prefetch A chunk 0 into regs
    float4 pA[8];
    #pragma unroll
    for (int it = 0; it < 8; it++) {
        int f = tid + 256 * it, rr = f >> 4, c4 = f & 15;
        pA[it] = *(const float4*)&x[(size_t)(row0 + rr) * DMODEL + c4 * 4];
    }
    // cp.async B chunk 0 into buf 0
    {
        #pragma unroll
        for (int j = 0; j < 2; j++) {
            int i = tid + 256 * j;              // 0..511
            int n = i >> 3, o = i & 7;
            size_t so = (size_t)n * DMODEL + o * 8;
            uint32_t db = sb + 36864 + n * 144 + o * 16;
            CP16(db,        whi + so);
            CP16(db + 9216, wlo + so);
        }
        CP_COMMIT();
    }

    for (int c = 0; c < 16; c++) {
        const int buf = c & 1;
        CP_WAIT0();
        __syncthreads();     // all warps done with prev MMA (A smem + other B buf free)

        // ---- STS A(c) from prefetch regs (cvt to hi/lo) ----
        #pragma unroll
        for (int it = 0; it < 8; it++) {
            int f  = tid + 256 * it, rr = f >> 4, c4 = f & 15;
            float4 v0 = pA[it];
            uint32_t h0 = pack_bf16x2_hi(v0.x, v0.y);
            uint32_t h1 = pack_bf16x2_hi(v0.z, v0.w);
            __nv_bfloat162 hh0 = *(__nv_bfloat162*)&h0;
            __nv_bfloat162 hh1 = *(__nv_bfloat162*)&h1;
            uint32_t l0 = pack_bf16x2_hi(v0.x - __bfloat162float(hh0.x),
                                         v0.y - __bfloat162float(hh0.y));
            uint32_t l1 = pack_bf16x2_hi(v0.z - __bfloat162float(hh1.x),
                                         v0.w - __bfloat162float(hh1.y));
            *(uint2*)&Ah[rr * 72 + c4 * 4] = make_uint2(h0, h1);
            *(uint2*)&Al[rr * 72 + c4 * 4] = make_uint2(l0, l1);
        }

        // ---- prefetch A(c+1) regs + cp.async B(c+1) into other buf ----
        if (c < 15) {
            const int k1 = (c + 1) * 64;
            #pragma unroll
            for (int it = 0; it < 8; it++) {
                int f = tid + 256 * it, rr = f >> 4, c4 = f & 15;
                pA[it] = *(const float4*)&x[(size_t)(row0 + rr) * DMODEL + k1 + c4 * 4];
            }
            #pragma unroll
            for (int j = 0; j < 2; j++) {
                int i = tid + 256 * j;
                int n = i >> 3, o = i & 7;
                size_t so = (size_t)n * DMODEL + k1 + o * 8;
                uint32_t db = sb + 36864 + (buf ^ 1) * 18432 + n * 144 + o * 16;
                CP16(db,        whi + so);
                CP16(db + 9216, wlo + so);
            }
            CP_COMMIT();
        }
        __syncthreads();     // A(c) staged before MMA reads

        // ---- MMA: 4 k-steps x 8 n-tiles x 3 pairings ----
        const __nv_bfloat16* Bh = (const __nv_bfloat16*)(smem + 36864 + buf * 18432);
        const __nv_bfloat16* Bl = (const __nv_bfloat16*)(smem + 36864 + buf * 18432 + 9216);
        const int ar0 = (warp * 16 + g) * 72;
        const int ar1 = (warp * 16 + g + 8) * 72;
        #pragma unroll
        for (int ks = 0; ks < 4; ks++) {
            const int kb = ks * 16 + qd * 2;
            uint32_t ah[4], al[4];
            ah[0] = *(uint32_t*)&Ah[ar0 + kb];
            ah[1] = *(uint32_t*)&Ah[ar1 + kb];
            ah[2] = *(uint32_t*)&Ah[ar0 + kb + 8];
            ah[3] = *(uint32_t*)&Ah[ar1 + kb + 8];
            al[0] = *(uint32_t*)&Al[ar0 + kb];
            al[1] = *(uint32_t*)&Al[ar1 + kb];
            al[2] = *(uint32_t*)&Al[ar0 + kb + 8];
            al[3] = *(uint32_t*)&Al[ar1 + kb + 8];
            #pragma unroll
            for (int nt = 0; nt < 8; nt++) {
                const int br = (nt * 8 + g) * 72;
                uint32_t bh[2], bl[2];
                bh[0] = *(uint32_t*)&Bh[br + kb];
                bh[1] = *(uint32_t*)&Bh[br + kb + 8];
                bl[0] = *(uint32_t*)&Bl[br + kb];
                bl[1] = *(uint32_t*)&Bl[br + kb + 8];
                mma16816(acc[nt], ah, bh);
                mma16816(acc[nt], ah, bl);
                mma16816(acc[nt], al, bh);
            }
        }
    }

    // ---- epilogue: write bf16 hi/lo pairs ----
    const int r0 = row0 + warp * 16 + g;
    #pragma unroll
    for (int nt = 0; nt < 8; nt++) {
        const int col = nt * 8 + qd * 2;
        uint32_t h, l;
        __nv_bfloat162 hv;
        h = pack_bf16x2_hi(acc[nt][0], acc[nt][1]);
        hv = *(__nv_bfloat162*)&h;
        l = pack_bf16x2_hi(acc[nt][0] - __bfloat162float(hv.x),
                           acc[nt][1] - __bfloat162float(hv.y));
        *(uint32_t*)&ohi[(size_t)r0 * HEAD + col] = h;
        *(uint32_t*)&olo[(size_t)r0 * HEAD + col] = l;
        h = pack_bf16x2_hi(acc[nt][2], acc[nt][3]);
        hv = *(__nv_bfloat162*)&h;
        l = pack_bf16x2_hi(acc[nt][2] - __bfloat162float(hv.x),
                           acc[nt][3] - __bfloat162float(hv.y));
        *(uint32_t*)&ohi[(size_t)(r0 + 8) * HEAD + col] = h;
        *(uint32_t*)&olo[(size_t)(r0 + 8) * HEAD + col] = l;
    }
}

// ===========================================================================
// Kernel 2: split-KV causal flash attention; Q/K/V pre-converted bf16 hi/lo
// staged via cp.async double-buffer. One __syncthreads per KV tile.
// ===========================================================================
// smem: Qh[128][72] @0 | Ql @18432 | KVbuf{0,1} @36864+buf*36864:
//       {Kh @+0, Kl @+9216, Vh @+18432, Vl @+27648}
#define ATTN_SMEM2 110592

__global__ __launch_bounds__(256, 2) void attn_partial_mma()
{
    extern __shared__ char smem[];
    const uint32_t sb = smem_u32(smem);
    const __nv_bfloat16* Qh = (const __nv_bfloat16*)(smem);
    const __nv_bfloat16* Ql = (const __nv_bfloat16*)(smem + 18432);

    const int b  = blockIdx.y;
    const int bx = blockIdx.x;
    int t, c;
    if      (bx <  8) { t = bx; c = 0; }
    else if (bx < 24) { int u = bx - 8;  t =  8 + (u >> 1); c = u & 1; }
    else if (bx < 48) { int u = bx - 24; t = 16 + u / 3;    c = u % 3; }
    else              { int u = bx - 48; t = 24 + (u >> 2); c = u & 3; }

    const int n_begin = c * 16;
    int n_end = 2 * t + 1;
    if (n_end > n_begin + 15) n_end = n_begin + 15;

    const int tid  = threadIdx.x;
    const int warp = tid >> 5;
    const int lane = tid & 31;
    const int g    = lane >> 2;
    const int qd   = lane & 3;
    const int qrow = t * 128 + warp * 16;

    const size_t bofs = (size_t)b * SEQ * HEAD;
    const __nv_bfloat16* qhi = g_qhi + bofs;
    const __nv_bfloat16* qlo = g_qlo + bofs;
    const __nv_bfloat16* khi = g_khi + bofs;
    const __nv_bfloat16* klo = g_klo + bofs;
    const __nv_bfloat16* vhi = g_vhi + bofs;
    const __nv_bfloat16* vlo = g_vlo + bofs;

    // ---- prologue: cp.async Q (once) + first KV tile into buf 0 ----
    #pragma unroll
    for (int j = 0; j < 4; j++) {
        int i = tid + 256 * j;                // 0..1023: 128 rows x 8 chunks
        int row = i >> 3, o = i & 7;
        size_t so = (size_t)(t * 128 + row) * HEAD + o * 8;
        uint32_t db = sb + row * 144 + o * 16;
        CP16(db,         qhi + so);
        CP16(db + 18432, qlo + so);
    }
    #pragma unroll
    for (int j = 0; j < 2; j++) {
        int i = tid + 256 * j;                // 0..511: 64 rows x 8 chunks
        int row = i >> 3, o = i & 7;
        size_t so = (size_t)(n_begin * 64 + row) * HEAD + o * 8;
        uint32_t db = sb + 36864 + row * 144 + o * 16;
        CP16(db,         khi + so);
        CP16(db +  9216, klo + so);
        CP16(db + 18432, vhi + so);
        CP16(db + 27648, vlo + so);
    }
    CP_COMMIT();

    float oa[8][4];
    #pragma unroll
    for (int nt = 0; nt < 8; nt++)
        #pragma unroll
        for (int i = 0; i < 4; i++) oa[nt][i] = 0.0f;
    float m0 = -1e30f, m1 = -1e30f, l0r = 0.0f, l1r = 0.0f;

    for (int n0 = n_begin; n0 <= n_end; n0++) {
        const int buf = (n0 - n_begin) & 1;
        CP_WAIT0();
        __syncthreads();   // tile n0 (and Q on first iter) visible; prev compute done

        // ---- cp.async next KV tile into other buf ----
        if (n0 < n_end) {
            #pragma unroll
            for (int j = 0; j < 2; j++) {
                int i = tid + 256 * j;
                int row = i >> 3, o = i & 7;
                size_t so = (size_t)((n0 + 1) * 64 + row) * HEAD + o * 8;
                uint32_t db = sb + 36864 + (buf ^ 1) * 36864 + row * 144 + o * 16;
                CP16(db,         khi + so);
                CP16(db +  9216, klo + so);
                CP16(db + 18432, vhi + so);
                CP16(db + 27648, vlo + so);
            }
            CP_COMMIT();
        }

        const __nv_bfloat16* Kh = (const __nv_bfloat16*)(smem + 36864 + buf * 36864);
        const __nv_bfloat16* Kl = (const __nv_bfloat16*)(smem + 36864 + buf * 36864 + 9216);
        const unsigned short* Vh = (const unsigned short*)(smem + 36864 + buf * 36864 + 18432);
        const unsigned short* Vl = (const unsigned short*)(smem + 36864 + buf * 36864 + 27648);

        // ---- S = Q K^T (3-term bf16 split) ----
        float s[8][4];
        #pragma unroll
        for (int nt = 0; nt < 8; nt++)
            #pragma unroll
            for (int i = 0; i < 4; i++) s[nt][i] = 0.0f;

        const int ar0 = (warp * 16 + g) * 72;
        const int ar1 = (warp * 16 + g + 8) * 72;
        #pragma unroll
        for (int ks = 0; ks < 4; ks++) {
            const int kb = ks * 16 + qd * 2;
            uint32_t ah[4], al[4];
            ah[0] = *(uint32_t*)&Qh[ar0 + kb];
            ah[1] = *(uint32_t*)&Qh[ar1 + kb];
            ah[2] = *(uint32_t*)&Qh[ar0 + kb + 8];
            ah[3] = *(uint32_t*)&Qh[ar1 + kb + 8];
            al[0] = *(uint32_t*)&Ql[ar0 + kb];
            al[1] = *(uint32_t*)&Ql[ar1 + kb];
            al[2] = *(uint32_t*)&Ql[ar0 + kb + 8];
            al[3] = *(uint32_t*)&Ql[ar1 + kb + 8];
            #pragma unroll
            for (int nt = 0; nt < 8; nt++) {
                const int br = (nt * 8 + g) * 72;
                uint32_t bh[2], bl[2];
                bh[0] = *(uint32_t*)&Kh[br + kb];
                bh[1] = *(uint32_t*)&Kh[br + kb + 8];
                bl[0] = *(uint32_t*)&Kl[br + kb];
                bl[1] = *(uint32_t*)&Kl[br + kb + 8];
                mma16816(s[nt], ah, bh);
                mma16816(s[nt], ah, bl);
                mma16816(s[nt], al, bh);
            }
        }

        // ---- scale + causal mask ----
        const float scale = 0.125f;   // 1/sqrt(64)
        const bool needm = (n0 * 64 + 63) > qrow;
        const int r0 = qrow + g, r1 = qrow + g + 8;
        #pragma unroll
        for (int nt = 0; nt < 8; nt++) {
            const int col0 = n0 * 64 + nt * 8 + qd * 2;
            s[nt][0] *= scale; s[nt][1] *= scale;
            s[nt][2] *= scale; s[nt][3] *= scale;
            if (needm) {
                if (col0     > r0) s[nt][0] = -1e30f;
                if (col0 + 1 > r0) s[nt][1] = -1e30f;
                if (col0     > r1) s[nt][2] = -1e30f;
                if (col0 + 1 > r1) s[nt][3] = -1e30f;
            }
        }

        // ---- online softmax (rows g, g+8; reduce across quad lanes) ----
        float mx0 = -1e30f, mx1 = -1e30f;
        #pragma unroll
        for (int nt = 0; nt < 8; nt++) {
            mx0 = fmaxf(mx0, fmaxf(s[nt][0], s[nt][1]));
            mx1 = fmaxf(mx1, fmaxf(s[nt][2], s[nt][3]));
        }
        mx0 = fmaxf(mx0, __shfl_xor_sync(0xffffffffu, mx0, 1));
        mx0 = fmaxf(mx0, __shfl_xor_sync(0xffffffffu, mx0, 2));
        mx1 = fmaxf(mx1, __shfl_xor_sync(0xffffffffu, mx1, 1));
        mx1 = fmaxf(mx1, __shfl_xor_sync(0xffffffffu, mx1, 2));
        const float mn0 = fmaxf(m0, mx0), mn1 = fmaxf(m1, mx1);
        const float corr0 = __expf(m0 - mn0), corr1 = __expf(m1 - mn1);
        m0 = mn0; m1 = mn1;

        float rs0 = 0.0f, rs1 = 0.0f;
        #pragma unroll
        for (int nt = 0; nt < 8; nt++) {
            s[nt][0] = __expf(s[nt][0] - mn0);
            s[nt][1] = __expf(s[nt][1] - mn0);
            s[nt][2] = __expf(s[nt][2] - mn1);
            s[nt][3] = __expf(s[nt][3] - mn1);
            rs0 += s[nt][0] + s[nt][1];
            rs1 += s[nt][2] + s[nt][3];
        }
        rs0 += __shfl_xor_sync(0xffffffffu, rs0, 1);
        rs0 += __shfl_xor_sync(0xffffffffu, rs0, 2);
        rs1 += __shfl_xor_sync(0xffffffffu, rs1, 1);
        rs1 += __shfl_xor_sync(0xffffffffu, rs1, 2);
        l0r = l0r * corr0 + rs0;
        l1r = l1r * corr1 + rs1;
        #pragma unroll
        for (int nt = 0; nt < 8; nt++) {
            oa[nt][0] *= corr0; oa[nt][1] *= corr0;
            oa[nt][2] *= corr1; oa[nt][3] *= corr1;
        }

        // ---- O += P V (P fragments built in-register, hi/lo split) ----
        #pragma unroll
        for (int kk = 0; kk < 4; kk++) {
            uint32_t pa[4], pl[4];
            {
                uint32_t h;
                __nv_bfloat162 hv;
                h = pack_bf16x2_hi(s[2*kk][0], s[2*kk][1]);   hv = *(__nv_bfloat162*)&h;
                pa[0] = h;
                pl[0] = pack_bf16x2_hi(s[2*kk][0] - __bfloat162float(hv.x),
                                       s[2*kk][1] - __bfloat162float(hv.y));
                h = pack_bf16x2_hi(s[2*kk][2], s[2*kk][3]);   hv = *(__nv_bfloat162*)&h;
                pa[1] = h;
                pl[1] = pack_bf16x2_hi(s[2*kk][2] - __bfloat162float(hv.x),
                                       s[2*kk][3] - __bfloat162float(hv.y));
                h = pack_bf16x2_hi(s[2*kk+1][0], s[2*kk+1][1]); hv = *(__nv_bfloat162*)&h;
                pa[2] = h;
                pl[2] = pack_bf16x2_hi(s[2*kk+1][0] - __bfloat162float(hv.x),
                                       s[2*kk+1][1] - __bfloat162float(hv.y));
                h = pack_bf16x2_hi(s[2*kk+1][2], s[2*kk+1][3]); hv = *(__nv_bfloat162*)&h;
                pa[3] = h;
                pl[3] = pack_bf16x2_hi(s[2*kk+1][2] - __bfloat162float(hv.x),
                                       s[2*kk+1][3] - __bfloat162float(hv.y));
            }
            const int kbase = kk * 16 + qd * 2;
            #pragma unroll
            for (int nt = 0; nt < 8; nt++) {
                const int ha = nt * 8 + g;
                uint32_t vbh[2], vbl[2];
                vbh[0] = (uint32_t)Vh[(kbase)     * 72 + ha] |
                         ((uint32_t)Vh[(kbase + 1) * 72 + ha] << 16);
                vbh[1] = (uint32_t)Vh[(kbase + 8) * 72 + ha] |
                         ((uint32_t)Vh[(kbase + 9) * 72 + ha] << 16);
                vbl[0] = (uint32_t)Vl[(kbase)     * 72 + ha] |
                         ((uint32_t)Vl[(kbase + 1) * 72 + ha] << 16);
                vbl[1] = (uint32_t)Vl[(kbase + 8) * 72 + ha] |
                         ((uint32_t)Vl[(kbase + 9) * 72 + ha] << 16);
                mma16816(oa[nt], pa, vbh);
                mma16816(oa[nt], pl, vbh);
                mma16816(oa[nt], pa, vbl);
            }
        }
    }

    // ---- epilogue: write unnormalized partial O and (m, l) ----
    const int slot = (b * QT2 + t) * MAXC + c;
    float* po = g_po + (size_t)slot * (128 * 64);
    const int orow0 = warp * 16 + g;
    #pragma unroll
    for (int nt = 0; nt < 8; nt++) {
        const int col = nt * 8 + qd * 2;
        *(float2*)&po[(orow0)     * 64 + col] = make_float2(oa[nt][0], oa[nt][1]);
        *(float2*)&po[(orow0 + 8) * 64 + col] = make_float2(oa[nt][2], oa[nt][3]);
    }
    if (qd == 0) {
        g_pm[slot * 128 + orow0]     = m0;
        g_pm[slot * 128 + orow0 + 8] = m1;
        g_pl[slot * 128 + orow0]     = l0r;
        g_pl[slot * 128 + orow0 + 8] = l1r;
    }
}

// ---------------------------------------------------------------------------
// Kernel 3: merge split-KV partials. One block per (t, b), 128 rows.
// ---------------------------------------------------------------------------
__global__ __launch_bounds__(256) void attn_merge_kernel(float* __restrict__ out)
{
    const int b  = blockIdx.y;
    const int t  = blockIdx.x;
    const int nc = (2 * t + 17) >> 4;   // ceil((2t+2)/16)

    const int tid = threadIdx.x;
    const int tx  = tid & 15;
    const int ty  = tid >> 4;

    const int slot0 = (b * QT2 + t) * MAXC;

    #pragma unroll
    for (int i = 0; i < 8; i++) {
        const int r = ty * 8 + i;
        float M = -1e30f;
        for (int c = 0; c < nc; c++)
            M = fmaxf(M, g_pm[(slot0 + c) * 128 + r]);
        float L = 0.0f;
        float w[MAXC];
        for (int c = 0; c < nc; c++) {
            w[c] = __expf(g_pm[(slot0 + c) * 128 + r] - M);
            L += w[c] * g_pl[(slot0 + c) * 128 + r];
        }
        float4 acc = make_float4(0.f, 0.f, 0.f, 0.f);
        for (int c = 0; c < nc; c++) {
            const float4 v = *(const float4*)&g_po[(size_t)(slot0 + c) * (128 * 64) + r * 64 + tx * 4];
            acc.x += w[c] * v.x; acc.y += w[c] * v.y;
            acc.z += w[c] * v.z; acc.w += w[c] * v.w;
        }
        const float inv = 1.0f / L;
        acc.x *= inv; acc.y *= inv; acc.z *= inv; acc.w *= inv;
        *(float4*)&out[((size_t)b * SEQ + t * 128 + r) * HEAD + tx * 4] = acc;
    }
}

// ---------------------------------------------------------------------------
extern "C" void kernel_launch(void* const* d_in, const int* in_sizes, int n_in,
                              void* d_out, int out_size)
{
    const float* q  = (const float*)d_in[0];
    const float* k  = (const float*)d_in[1];
    const float* v  = (const float*)d_in[2];
    const float* wq = (const float*)d_in[3];
    const float* wk = (const float*)d_in[4];
    const float* wv = (const float*)d_in[5];
    float* out = (float*)d_out;

    cudaFuncSetAttribute(proj_mma_kernel, cudaFuncAttributeMaxDynamicSharedMemorySize, PROJ_SMEM);
    cudaFuncSetAttribute(attn_partial_mma, cudaFuncAttributeMaxDynamicSharedMemorySize, ATTN_SMEM2);

    // one-time W transpose + bf16 hi/lo conversion
    conv_w_kernel<<<dim3(64, 3), 256>>>(wq, wk, wv);

    // projections: 128-row tiles, grid.z selects q/k/v; outputs bf16 hi/lo
    proj_mma_kernel<<<dim3((BATCH * SEQ) / 128, 1, 3), 256, PROJ_SMEM>>>(q, k, v);

    // split-KV partials: 80 (t,chunk) pairs per batch
    attn_partial_mma<<<dim3(80, BATCH), 256, ATTN_SMEM2>>>();

    // merge: one block per 128-row query tile per batch
    attn_merge_kernel<<<dim3(QT2, BATCH), 256>>>(out);
}

// round 17
// speedup vs baseline: 4.8057x; 1.0202x over previous
#include <cuda_runtime.h>
#include <cuda_bf16.h>
#include <cstdint>

// Problem constants
#define BATCH   4
#define SEQ     4096
#define DMODEL  1024
#define HEAD    64
#define QT2     32          // SEQ / 128 query tiles per batch (mma attention)
#define NTILES  64
#define MAXC    4

// Projected heads as bf16 hi/lo pairs (written by proj, read by attention)
#define NELEM (BATCH * SEQ * HEAD)
__device__ __align__(16) __nv_bfloat16 g_qhi[NELEM], g_qlo[NELEM];
__device__ __align__(16) __nv_bfloat16 g_khi[NELEM], g_klo[NELEM];
__device__ __align__(16) __nv_bfloat16 g_vhi[NELEM], g_vlo[NELEM];

// W transposed bf16 hi/lo: [z][n][k]
__device__ __align__(16) __nv_bfloat16 g_wthi[3 * HEAD * DMODEL];
__device__ __align__(16) __nv_bfloat16 g_wtlo[3 * HEAD * DMODEL];

// Split-KV partials (128-row tiles): O unnorm [b][t][c][128][64], m/l [b][t][c][128]
__device__ float g_po[(size_t)BATCH * NTILES * MAXC * 64 * 64];
__device__ float g_pm[BATCH * NTILES * MAXC * 64];
__device__ float g_pl[BATCH * NTILES * MAXC * 64];

// ---------------------------------------------------------------------------
// PTX helpers (all baseline ISA, valid on plain sm_103 target)
// ---------------------------------------------------------------------------
__device__ __forceinline__ void mma16816(float* c, const uint32_t* a, const uint32_t* b) {
    asm volatile(
        "mma.sync.aligned.m16n8k16.row.col.f32.bf16.bf16.f32 "
        "{%0,%1,%2,%3}, {%4,%5,%6,%7}, {%8,%9}, {%0,%1,%2,%3};"
        : "+f"(c[0]), "+f"(c[1]), "+f"(c[2]), "+f"(c[3])
        : "r"(a[0]), "r"(a[1]), "r"(a[2]), "r"(a[3]), "r"(b[0]), "r"(b[1]));
}

__device__ __forceinline__ uint32_t pack_bf16x2_hi(float a, float b) {
    __nv_bfloat162 h = __floats2bfloat162_rn(a, b);
    return *(uint32_t*)&h;
}

__device__ __forceinline__ uint32_t smem_u32(const void* p) {
    uint32_t a;
    asm("{ .reg .u64 t; cvta.to.shared.u64 t, %1; cvt.u32.u64 %0, t; }"
        : "=r"(a) : "l"(p));
    return a;
}

#define CP16(dst_u32, src_ptr) \
    asm volatile("cp.async.cg.shared.global [%0], [%1], 16;" \
                 :: "r"(dst_u32), "l"(src_ptr))
#define CP_COMMIT() asm volatile("cp.async.commit_group;" ::: "memory")
#define CP_WAIT0()  asm volatile("cp.async.wait_group 0;" ::: "memory")

// ===========================================================================
// Kernel 0: one-time W -> transposed bf16 hi/lo.  wt[z][n][k] = w[z][k][n]
// ===========================================================================
__global__ __launch_bounds__(256) void conv_w_kernel(
    const float* __restrict__ wq, const float* __restrict__ wk, const float* __restrict__ wv)
{
    const int z = blockIdx.y;
    const float* w = (z == 0) ? wq : (z == 1) ? wk : wv;
    __nv_bfloat16* oh = g_wthi + (size_t)z * HEAD * DMODEL;
    __nv_bfloat16* ol = g_wtlo + (size_t)z * HEAD * DMODEL;

    const int idx = blockIdx.x * 256 + threadIdx.x;   // 0..16383 over (k, n4)
    const int k  = idx >> 4;
    const int n4 = idx & 15;
    float4 v = *(const float4*)&w[(size_t)k * HEAD + n4 * 4];
    float vals[4] = {v.x, v.y, v.z, v.w};
    #pragma unroll
    for (int j = 0; j < 4; j++) {
        __nv_bfloat16 h = __float2bfloat16(vals[j]);
        __nv_bfloat16 l = __float2bfloat16(vals[j] - __bfloat162float(h));
        oh[(size_t)(n4 * 4 + j) * DMODEL + k] = h;
        ol[(size_t)(n4 * 4 + j) * DMODEL + k] = l;
    }
}

// ===========================================================================
// Kernel 1: mma.sync bf16-split projections. (unchanged from R16)
// ===========================================================================
// smem: Ah[128][72]bf16 @0 | Al @18432 | Bbuf{0,1} @36864+buf*18432 {Bh, Bl@+9216}
#define PROJ_SMEM 73728

__global__ __launch_bounds__(256, 2) void proj_mma_kernel(
    const float* __restrict__ q, const float* __restrict__ k, const float* __restrict__ v)
{
    extern __shared__ char smem[];
    const uint32_t sb = smem_u32(smem);
    __nv_bfloat16* Ah = (__nv_bfloat16*)(smem);
    __nv_bfloat16* Al = (__nv_bfloat16*)(smem + 18432);

    const int z = blockIdx.z;
    const float* x = (z == 0) ? q : (z == 1) ? k : v;
    const __nv_bfloat16* whi = g_wthi + (size_t)z * HEAD * DMODEL;
    const __nv_bfloat16* wlo = g_wtlo + (size_t)z * HEAD * DMODEL;
    __nv_bfloat16* ohi = (z == 0) ? g_qhi : (z == 1) ? g_khi : g_vhi;
    __nv_bfloat16* olo = (z == 0) ? g_qlo : (z == 1) ? g_klo : g_vlo;

    const int row0 = blockIdx.x * 128;
    const int tid  = threadIdx.x;
    const int warp = tid >> 5;
    const int lane = tid & 31;
    const int g    = lane >> 2;
    const int qd   = lane & 3;

    float acc[8][4];
    #pragma unroll
    for (int nt = 0; nt < 8; nt++)
        #pragma unroll
        for (int i = 0; i < 4; i++) acc[nt][i] = 0.0f;

    // prefetch A chunk 0 into regs
    float4 pA[8];
    #pragma unroll
    for (int it = 0; it < 8; it++) {
        int f = tid + 256 * it, rr = f >> 4, c4 = f & 15;
        pA[it] = *(const float4*)&x[(size_t)(row0 + rr) * DMODEL + c4 * 4];
    }
    // cp.async B chunk 0 into buf 0
    {
        #pragma unroll
        for (int j = 0; j < 2; j++) {
            int i = tid + 256 * j;              // 0..511
            int n = i >> 3, o = i & 7;
            size_t so = (size_t)n * DMODEL + o * 8;
            uint32_t db = sb + 36864 + n * 144 + o * 16;
            CP16(db,        whi + so);
            CP16(db + 9216, wlo + so);
        }
        CP_COMMIT();
    }

    for (int c = 0; c < 16; c++) {
        const int buf = c & 1;
        CP_WAIT0();
        __syncthreads();     // all warps done with prev MMA (A smem + other B buf free)

        // ---- STS A(c) from prefetch regs (cvt to hi/lo) ----
        #pragma unroll
        for (int it = 0; it < 8; it++) {
            int f  = tid + 256 * it, rr = f >> 4, c4 = f & 15;
            float4 v0 = pA[it];
            uint32_t h0 = pack_bf16x2_hi(v0.x, v0.y);
            uint32_t h1 = pack_bf16x2_hi(v0.z, v0.w);
            __nv_bfloat162 hh0 = *(__nv_bfloat162*)&h0;
            __nv_bfloat162 hh1 = *(__nv_bfloat162*)&h1;
            uint32_t l0 = pack_bf16x2_hi(v0.x - __bfloat162float(hh0.x),
                                         v0.y - __bfloat162float(hh0.y));
            uint32_t l1 = pack_bf16x2_hi(v0.z - __bfloat162float(hh1.x),
                                         v0.w - __bfloat162float(hh1.y));
            *(uint2*)&Ah[rr * 72 + c4 * 4] = make_uint2(h0, h1);
            *(uint2*)&Al[rr * 72 + c4 * 4] = make_uint2(l0, l1);
        }

        // ---- prefetch A(c+1) regs + cp.async B(c+1) into other buf ----
        if (c < 15) {
            const int k1 = (c + 1) * 64;
            #pragma unroll
            for (int it = 0; it < 8; it++) {
                int f = tid + 256 * it, rr = f >> 4, c4 = f & 15;
                pA[it] = *(const float4*)&x[(size_t)(row0 + rr) * DMODEL + k1 + c4 * 4];
            }
            #pragma unroll
            for (int j = 0; j < 2; j++) {
                int i = tid + 256 * j;
                int n = i >> 3, o = i & 7;
                size_t so = (size_t)n * DMODEL + k1 + o * 8;
                uint32_t db = sb + 36864 + (buf ^ 1) * 18432 + n * 144 + o * 16;
                CP16(db,        whi + so);
                CP16(db + 9216, wlo + so);
            }
            CP_COMMIT();
        }
        __syncthreads();     // A(c) staged before MMA reads

        // ---- MMA: 4 k-steps x 8 n-tiles x 3 pairings ----
        const __nv_bfloat16* Bh = (const __nv_bfloat16*)(smem + 36864 + buf * 18432);
        const __nv_bfloat16* Bl = (const __nv_bfloat16*)(smem + 36864 + buf * 18432 + 9216);
        const int ar0 = (warp * 16 + g) * 72;
        const int ar1 = (warp * 16 + g + 8) * 72;
        #pragma unroll
        for (int ks = 0; ks < 4; ks++) {
            const int kb = ks * 16 + qd * 2;
            uint32_t ah[4], al[4];
            ah[0] = *(uint32_t*)&Ah[ar0 + kb];
            ah[1] = *(uint32_t*)&Ah[ar1 + kb];
            ah[2] = *(uint32_t*)&Ah[ar0 + kb + 8];
            ah[3] = *(uint32_t*)&Ah[ar1 + kb + 8];
            al[0] = *(uint32_t*)&Al[ar0 + kb];
            al[1] = *(uint32_t*)&Al[ar1 + kb];
            al[2] = *(uint32_t*)&Al[ar0 + kb + 8];
            al[3] = *(uint32_t*)&Al[ar1 + kb + 8];
            #pragma unroll
            for (int nt = 0; nt < 8; nt++) {
                const int br = (nt * 8 + g) * 72;
                uint32_t bh[2], bl[2];
                bh[0] = *(uint32_t*)&Bh[br + kb];
                bh[1] = *(uint32_t*)&Bh[br + kb + 8];
                bl[0] = *(uint32_t*)&Bl[br + kb];
                bl[1] = *(uint32_t*)&Bl[br + kb + 8];
                mma16816(acc[nt], ah, bh);
                mma16816(acc[nt], ah, bl);
                mma16816(acc[nt], al, bh);
            }
        }
    }

    // ---- epilogue: write bf16 hi/lo pairs ----
    const int r0 = row0 + warp * 16 + g;
    #pragma unroll
    for (int nt = 0; nt < 8; nt++) {
        const int col = nt * 8 + qd * 2;
        uint32_t h, l;
        __nv_bfloat162 hv;
        h = pack_bf16x2_hi(acc[nt][0], acc[nt][1]);
        hv = *(__nv_bfloat162*)&h;
        l = pack_bf16x2_hi(acc[nt][0] - __bfloat162float(hv.x),
                           acc[nt][1] - __bfloat162float(hv.y));
        *(uint32_t*)&ohi[(size_t)r0 * HEAD + col] = h;
        *(uint32_t*)&olo[(size_t)r0 * HEAD + col] = l;
        h = pack_bf16x2_hi(acc[nt][2], acc[nt][3]);
        hv = *(__nv_bfloat162*)&h;
        l = pack_bf16x2_hi(acc[nt][2] - __bfloat162float(hv.x),
                           acc[nt][3] - __bfloat162float(hv.y));
        *(uint32_t*)&ohi[(size_t)(r0 + 8) * HEAD + col] = h;
        *(uint32_t*)&olo[(size_t)(r0 + 8) * HEAD + col] = l;
    }
}

// ===========================================================================
// Kernel 2: split-KV causal flash attention (cp.async double-buffer).
// NEW: t<=7 blocks (nc==1) normalize and write directly to out.
// ===========================================================================
// smem: Qh[128][72] @0 | Ql @18432 | KVbuf{0,1} @36864+buf*36864:
//       {Kh @+0, Kl @+9216, Vh @+18432, Vl @+27648}
#define ATTN_SMEM2 110592

__global__ __launch_bounds__(256, 2) void attn_partial_mma(float* __restrict__ out)
{
    extern __shared__ char smem[];
    const uint32_t sb = smem_u32(smem);
    const __nv_bfloat16* Qh = (const __nv_bfloat16*)(smem);
    const __nv_bfloat16* Ql = (const __nv_bfloat16*)(smem + 18432);

    const int b  = blockIdx.y;
    const int bx = blockIdx.x;
    int t, c;
    if      (bx <  8) { t = bx; c = 0; }
    else if (bx < 24) { int u = bx - 8;  t =  8 + (u >> 1); c = u & 1; }
    else if (bx < 48) { int u = bx - 24; t = 16 + u / 3;    c = u % 3; }
    else              { int u = bx - 48; t = 24 + (u >> 2); c = u & 3; }

    const int n_begin = c * 16;
    int n_end = 2 * t + 1;
    if (n_end > n_begin + 15) n_end = n_begin + 15;

    const int tid  = threadIdx.x;
    const int warp = tid >> 5;
    const int lane = tid & 31;
    const int g    = lane >> 2;
    const int qd   = lane & 3;
    const int qrow = t * 128 + warp * 16;

    const size_t bofs = (size_t)b * SEQ * HEAD;
    const __nv_bfloat16* qhi = g_qhi + bofs;
    const __nv_bfloat16* qlo = g_qlo + bofs;
    const __nv_bfloat16* khi = g_khi + bofs;
    const __nv_bfloat16* klo = g_klo + bofs;
    const __nv_bfloat16* vhi = g_vhi + bofs;
    const __nv_bfloat16* vlo = g_vlo + bofs;

    // ---- prologue: cp.async Q (once) + first KV tile into buf 0 ----
    #pragma unroll
    for (int j = 0; j < 4; j++) {
        int i = tid + 256 * j;                // 0..1023: 128 rows x 8 chunks
        int row = i >> 3, o = i & 7;
        size_t so = (size_t)(t * 128 + row) * HEAD + o * 8;
        uint32_t db = sb + row * 144 + o * 16;
        CP16(db,         qhi + so);
        CP16(db + 18432, qlo + so);
    }
    #pragma unroll
    for (int j = 0; j < 2; j++) {
        int i = tid + 256 * j;                // 0..511: 64 rows x 8 chunks
        int row = i >> 3, o = i & 7;
        size_t so = (size_t)(n_begin * 64 + row) * HEAD + o * 8;
        uint32_t db = sb + 36864 + row * 144 + o * 16;
        CP16(db,         khi + so);
        CP16(db +  9216, klo + so);
        CP16(db + 18432, vhi + so);
        CP16(db + 27648, vlo + so);
    }
    CP_COMMIT();

    float oa[8][4];
    #pragma unroll
    for (int nt = 0; nt < 8; nt++)
        #pragma unroll
        for (int i = 0; i < 4; i++) oa[nt][i] = 0.0f;
    float m0 = -1e30f, m1 = -1e30f, l0r = 0.0f, l1r = 0.0f;

    for (int n0 = n_begin; n0 <= n_end; n0++) {
        const int buf = (n0 - n_begin) & 1;
        CP_WAIT0();
        __syncthreads();   // tile n0 (and Q on first iter) visible; prev compute done

        // ---- cp.async next KV tile into other buf ----
        if (n0 < n_end) {
            #pragma unroll
            for (int j = 0; j < 2; j++) {
                int i = tid + 256 * j;
                int row = i >> 3, o = i & 7;
                size_t so = (size_t)((n0 + 1) * 64 + row) * HEAD + o * 8;
                uint32_t db = sb + 36864 + (buf ^ 1) * 36864 + row * 144 + o * 16;
                CP16(db,         khi + so);
                CP16(db +  9216, klo + so);
                CP16(db + 18432, vhi + so);
                CP16(db + 27648, vlo + so);
            }
            CP_COMMIT();
        }

        const __nv_bfloat16* Kh = (const __nv_bfloat16*)(smem + 36864 + buf * 36864);
        const __nv_bfloat16* Kl = (const __nv_bfloat16*)(smem + 36864 + buf * 36864 + 9216);
        const unsigned short* Vh = (const unsigned short*)(smem + 36864 + buf * 36864 + 18432);
        const unsigned short* Vl = (const unsigned short*)(smem + 36864 + buf * 36864 + 27648);

        // ---- S = Q K^T (3-term bf16 split) ----
        float s[8][4];
        #pragma unroll
        for (int nt = 0; nt < 8; nt++)
            #pragma unroll
            for (int i = 0; i < 4; i++) s[nt][i] = 0.0f;

        const int ar0 = (warp * 16 + g) * 72;
        const int ar1 = (warp * 16 + g + 8) * 72;
        #pragma unroll
        for (int ks = 0; ks < 4; ks++) {
            const int kb = ks * 16 + qd * 2;
            uint32_t ah[4], al[4];
            ah[0] = *(uint32_t*)&Qh[ar0 + kb];
            ah[1] = *(uint32_t*)&Qh[ar1 + kb];
            ah[2] = *(uint32_t*)&Qh[ar0 + kb + 8];
            ah[3] = *(uint32_t*)&Qh[ar1 + kb + 8];
            al[0] = *(uint32_t*)&Ql[ar0 + kb];
            al[1] = *(uint32_t*)&Ql[ar1 + kb];
            al[2] = *(uint32_t*)&Ql[ar0 + kb + 8];
            al[3] = *(uint32_t*)&Ql[ar1 + kb + 8];
            #pragma unroll
            for (int nt = 0; nt < 8; nt++) {
                const int br = (nt * 8 + g) * 72;
                uint32_t bh[2], bl[2];
                bh[0] = *(uint32_t*)&Kh[br + kb];
                bh[1] = *(uint32_t*)&Kh[br + kb + 8];
                bl[0] = *(uint32_t*)&Kl[br + kb];
                bl[1] = *(uint32_t*)&Kl[br + kb + 8];
                mma16816(s[nt], ah, bh);
                mma16816(s[nt], ah, bl);
                mma16816(s[nt], al, bh);
            }
        }

        // ---- scale + causal mask ----
        const float scale = 0.125f;   // 1/sqrt(64)
        const bool needm = (n0 * 64 + 63) > qrow;
        const int r0 = qrow + g, r1 = qrow + g + 8;
        #pragma unroll
        for (int nt = 0; nt < 8; nt++) {
            const int col0 = n0 * 64 + nt * 8 + qd * 2;
            s[nt][0] *= scale; s[nt][1] *= scale;
            s[nt][2] *= scale; s[nt][3] *= scale;
            if (needm) {
                if (col0     > r0) s[nt][0] = -1e30f;
                if (col0 + 1 > r0) s[nt][1] = -1e30f;
                if (col0     > r1) s[nt][2] = -1e30f;
                if (col0 + 1 > r1) s[nt][3] = -1e30f;
            }
        }

        // ---- online softmax (rows g, g+8; reduce across quad lanes) ----
        float mx0 = -1e30f, mx1 = -1e30f;
        #pragma unroll
        for (int nt = 0; nt < 8; nt++) {
            mx0 = fmaxf(mx0, fmaxf(s[nt][0], s[nt][1]));
            mx1 = fmaxf(mx1, fmaxf(s[nt][2], s[nt][3]));
        }
        mx0 = fmaxf(mx0, __shfl_xor_sync(0xffffffffu, mx0, 1));
        mx0 = fmaxf(mx0, __shfl_xor_sync(0xffffffffu, mx0, 2));
        mx1 = fmaxf(mx1, __shfl_xor_sync(0xffffffffu, mx1, 1));
        mx1 = fmaxf(mx1, __shfl_xor_sync(0xffffffffu, mx1, 2));
        const float mn0 = fmaxf(m0, mx0), mn1 = fmaxf(m1, mx1);
        const float corr0 = __expf(m0 - mn0), corr1 = __expf(m1 - mn1);
        m0 = mn0; m1 = mn1;

        float rs0 = 0.0f, rs1 = 0.0f;
        #pragma unroll
        for (int nt = 0; nt < 8; nt++) {
            s[nt][0] = __expf(s[nt][0] - mn0);
            s[nt][1] = __expf(s[nt][1] - mn0);
            s[nt][2] = __expf(s[nt][2] - mn1);
            s[nt][3] = __expf(s[nt][3] - mn1);
            rs0 += s[nt][0] + s[nt][1];
            rs1 += s[nt][2] + s[nt][3];
        }
        rs0 += __shfl_xor_sync(0xffffffffu, rs0, 1);
        rs0 += __shfl_xor_sync(0xffffffffu, rs0, 2);
        rs1 += __shfl_xor_sync(0xffffffffu, rs1, 1);
        rs1 += __shfl_xor_sync(0xffffffffu, rs1, 2);
        l0r = l0r * corr0 + rs0;
        l1r = l1r * corr1 + rs1;
        #pragma unroll
        for (int nt = 0; nt < 8; nt++) {
            oa[nt][0] *= corr0; oa[nt][1] *= corr0;
            oa[nt][2] *= corr1; oa[nt][3] *= corr1;
        }

        // ---- O += P V (P fragments built in-register, hi/lo split) ----
        #pragma unroll
        for (int kk = 0; kk < 4; kk++) {
            uint32_t pa[4], pl[4];
            {
                uint32_t h;
                __nv_bfloat162 hv;
                h = pack_bf16x2_hi(s[2*kk][0], s[2*kk][1]);   hv = *(__nv_bfloat162*)&h;
                pa[0] = h;
                pl[0] = pack_bf16x2_hi(s[2*kk][0] - __bfloat162float(hv.x),
                                       s[2*kk][1] - __bfloat162float(hv.y));
                h = pack_bf16x2_hi(s[2*kk][2], s[2*kk][3]);   hv = *(__nv_bfloat162*)&h;
                pa[1] = h;
                pl[1] = pack_bf16x2_hi(s[2*kk][2] - __bfloat162float(hv.x),
                                       s[2*kk][3] - __bfloat162float(hv.y));
                h = pack_bf16x2_hi(s[2*kk+1][0], s[2*kk+1][1]); hv = *(__nv_bfloat162*)&h;
                pa[2] = h;
                pl[2] = pack_bf16x2_hi(s[2*kk+1][0] - __bfloat162float(hv.x),
                                       s[2*kk+1][1] - __bfloat162float(hv.y));
                h = pack_bf16x2_hi(s[2*kk+1][2], s[2*kk+1][3]); hv = *(__nv_bfloat162*)&h;
                pa[3] = h;
                pl[3] = pack_bf16x2_hi(s[2*kk+1][2] - __bfloat162float(hv.x),
                                       s[2*kk+1][3] - __bfloat162float(hv.y));
            }
            const int kbase = kk * 16 + qd * 2;
            #pragma unroll
            for (int nt = 0; nt < 8; nt++) {
                const int ha = nt * 8 + g;
                uint32_t vbh[2], vbl[2];
                vbh[0] = (uint32_t)Vh[(kbase)     * 72 + ha] |
                         ((uint32_t)Vh[(kbase + 1) * 72 + ha] << 16);
                vbh[1] = (uint32_t)Vh[(kbase + 8) * 72 + ha] |
                         ((uint32_t)Vh[(kbase + 9) * 72 + ha] << 16);
                vbl[0] = (uint32_t)Vl[(kbase)     * 72 + ha] |
                         ((uint32_t)Vl[(kbase + 1) * 72 + ha] << 16);
                vbl[1] = (uint32_t)Vl[(kbase + 8) * 72 + ha] |
                         ((uint32_t)Vl[(kbase + 9) * 72 + ha] << 16);
                mma16816(oa[nt], pa, vbh);
                mma16816(oa[nt], pl, vbh);
                mma16816(oa[nt], pa, vbl);
            }
        }
    }

    if (t <= 7) {
        // nc == 1: this block covered the full causal range — write normalized out
        const float inv0 = 1.0f / l0r, inv1 = 1.0f / l1r;
        const size_t orow = (size_t)b * SEQ + qrow + g;
        #pragma unroll
        for (int nt = 0; nt < 8; nt++) {
            const int col = nt * 8 + qd * 2;
            *(float2*)&out[(orow)     * HEAD + col] = make_float2(oa[nt][0] * inv0, oa[nt][1] * inv0);
            *(float2*)&out[(orow + 8) * HEAD + col] = make_float2(oa[nt][2] * inv1, oa[nt][3] * inv1);
        }
    } else {
        // write unnormalized partial O and (m, l)
        const int slot = (b * QT2 + t) * MAXC + c;
        float* po = g_po + (size_t)slot * (128 * 64);
        const int orow0 = warp * 16 + g;
        #pragma unroll
        for (int nt = 0; nt < 8; nt++) {
            const int col = nt * 8 + qd * 2;
            *(float2*)&po[(orow0)     * 64 + col] = make_float2(oa[nt][0], oa[nt][1]);
            *(float2*)&po[(orow0 + 8) * 64 + col] = make_float2(oa[nt][2], oa[nt][3]);
        }
        if (qd == 0) {
            g_pm[slot * 128 + orow0]     = m0;
            g_pm[slot * 128 + orow0 + 8] = m1;
            g_pl[slot * 128 + orow0]     = l0r;
            g_pl[slot * 128 + orow0 + 8] = l1r;
        }
    }
}

// ---------------------------------------------------------------------------
// Kernel 3: merge split-KV partials for t >= 8 only.
// Grid (96, BATCH): bx -> (t = 8 + bx/4, 32-row slice = bx%4). 256 threads;
// thread owns one row x two float4 columns. No serial row loop.
// ---------------------------------------------------------------------------
__global__ __launch_bounds__(256) void attn_merge_kernel(float* __restrict__ out)
{
    const int b  = blockIdx.y;
    const int t  = 8 + (blockIdx.x >> 2);
    const int qr = (blockIdx.x & 3) * 32;
    const int nc = (2 * t + 17) >> 4;   // 2..4 for t in [8,31]

    const int tid = threadIdx.x;
    const int r   = qr + (tid >> 3);    // row within 128
    const int f4  = tid & 7;            // float4 col pair base

    const int slot0 = (b * QT2 + t) * MAXC;

    float M = -1e30f;
    #pragma unroll
    for (int c = 0; c < MAXC; c++)
        if (c < nc) M = fmaxf(M, g_pm[(slot0 + c) * 128 + r]);
    float L = 0.0f;
    float w[MAXC];
    #pragma unroll
    for (int c = 0; c < MAXC; c++) {
        if (c < nc) {
            w[c] = __expf(g_pm[(slot0 + c) * 128 + r] - M);
            L += w[c] * g_pl[(slot0 + c) * 128 + r];
        }
    }

    float4 a0 = make_float4(0.f, 0.f, 0.f, 0.f);
    float4 a1 = make_float4(0.f, 0.f, 0.f, 0.f);
    #pragma unroll
    for (int c = 0; c < MAXC; c++) {
        if (c < nc) {
            const float* base = g_po + (size_t)(slot0 + c) * (128 * 64) + r * 64;
            const float4 v0 = *(const float4*)&base[f4 * 4];
            const float4 v1 = *(const float4*)&base[(f4 + 8) * 4];
            a0.x += w[c] * v0.x; a0.y += w[c] * v0.y; a0.z += w[c] * v0.z; a0.w += w[c] * v0.w;
            a1.x += w[c] * v1.x; a1.y += w[c] * v1.y; a1.z += w[c] * v1.z; a1.w += w[c] * v1.w;
        }
    }
    const float inv = 1.0f / L;
    a0.x *= inv; a0.y *= inv; a0.z *= inv; a0.w *= inv;
    a1.x *= inv; a1.y *= inv; a1.z *= inv; a1.w *= inv;
    float* orow = out + ((size_t)b * SEQ + t * 128 + r) * HEAD;
    *(float4*)&orow[f4 * 4]       = a0;
    *(float4*)&orow[(f4 + 8) * 4] = a1;
}

// ---------------------------------------------------------------------------
extern "C" void kernel_launch(void* const* d_in, const int* in_sizes, int n_in,
                              void* d_out, int out_size)
{
    const float* q  = (const float*)d_in[0];
    const float* k  = (const float*)d_in[1];
    const float* v  = (const float*)d_in[2];
    const float* wq = (const float*)d_in[3];
    const float* wk = (const float*)d_in[4];
    const float* wv = (const float*)d_in[5];
    float* out = (float*)d_out;

    cudaFuncSetAttribute(proj_mma_kernel, cudaFuncAttributeMaxDynamicSharedMemorySize, PROJ_SMEM);
    cudaFuncSetAttribute(attn_partial_mma, cudaFuncAttributeMaxDynamicSharedMemorySize, ATTN_SMEM2);

    // one-time W transpose + bf16 hi/lo conversion
    conv_w_kernel<<<dim3(64, 3), 256>>>(wq, wk, wv);

    // projections: 128-row tiles, grid.z selects q/k/v; outputs bf16 hi/lo
    proj_mma_kernel<<<dim3((BATCH * SEQ) / 128, 1, 3), 256, PROJ_SMEM>>>(q, k, v);

    // split-KV partials: 80 (t,chunk) pairs per batch; t<=7 writes out directly
    attn_partial_mma<<<dim3(80, BATCH), 256, ATTN_SMEM2>>>(out);

    // merge t>=8: 4 row-slices per tile per batch
    attn_merge_kernel<<<dim3((QT2 - 8) * 4, BATCH), 256>>>(out);
}